// round 7
// baseline (speedup 1.0000x reference)
#include <cuda_runtime.h>
#include <cstdint>
#include <math.h>

// Problem constants
#define B_    2
#define T_    2048
#define D_    1024
#define H_    16
#define DH_   64
#define WIN_  256
#define E3_   3072          // 3*H*Dh
#define M_    (B_ * T_)     // 4096
#define SCALE_ 0.125f       // 64^-0.5

// Scratch (static device globals — allocation-free per harness rules)
__device__ float g_qkv[(size_t)M_ * E3_];     // [4096, 3072] natural, tf32-rounded
__device__ float g_att[(size_t)M_ * D_];      // [4096, 1024] k-PERMUTED, tf32-rounded
__device__ float g_xr[(size_t)M_ * D_];       // pre-rounded + k-permuted x
__device__ float g_wqkvr[(size_t)E3_ * D_];   // pre-rounded + k-permuted w_qkv
__device__ float g_woutr[(size_t)D_ * D_];    // pre-rounded + k-permuted w_out

// ===========================================================================
// Helpers
// ===========================================================================
__device__ __forceinline__ uint32_t smem_u32(const void* p) {
    uint32_t a;
    asm("{ .reg .u64 t; cvta.to.shared.u64 t, %1; cvt.u32.u64 %0, t; }" : "=r"(a) : "l"(p));
    return a;
}
__device__ __forceinline__ void cp_async16(uint32_t saddr, const void* gptr) {
    asm volatile("cp.async.cg.shared.global [%0], [%1], 16;" :: "r"(saddr), "l"(gptr));
}
#define CP_COMMIT() asm volatile("cp.async.commit_group;" ::: "memory")
#define CP_WAIT0()  asm volatile("cp.async.wait_group 0;" ::: "memory")
#define CP_WAIT1()  asm volatile("cp.async.wait_group 1;" ::: "memory")

__device__ __forceinline__ float tf32r(float f) {   // round-to-nearest onto tf32 grid
    uint32_t r;
    asm("cvt.rna.tf32.f32 %0, %1;" : "=r"(r) : "f"(f));
    return __uint_as_float(r);
}
__device__ __forceinline__ void mma_tf32(float* c, const uint32_t* a, const uint32_t* b) {
    asm volatile(
        "mma.sync.aligned.m16n8k8.row.col.f32.tf32.tf32.f32 "
        "{%0,%1,%2,%3}, {%4,%5,%6,%7}, {%8,%9}, {%0,%1,%2,%3};"
        : "+f"(c[0]), "+f"(c[1]), "+f"(c[2]), "+f"(c[3])
        : "r"(a[0]), "r"(a[1]), "r"(a[2]), "r"(a[3]), "r"(b[0]), "r"(b[1]));
}

// Fused pre-round + k-permute for all three GEMM operands, one launch.
// Permutes each 8-float k-group to [a0,a4,a1,a5,a2,a6,a3,a7].
#define NX8 (M_ * D_ / 8)
#define NW8 (E3_ * D_ / 8)
#define NO8 (D_ * D_ / 8)
__global__ void preround_all(const float* __restrict__ x,  const float* __restrict__ wq,
                             const float* __restrict__ wo, float* __restrict__ xr,
                             float* __restrict__ wqr,      float* __restrict__ wor) {
    int i = blockIdx.x * blockDim.x + threadIdx.x;
    const float* s; float* d; int j;
    if (i < NX8)            { s = x;  d = xr;  j = i; }
    else if (i < NX8 + NW8) { s = wq; d = wqr; j = i - NX8; }
    else if (i < NX8 + NW8 + NO8) { s = wo; d = wor; j = i - NX8 - NW8; }
    else return;
    const float4 v0 = ((const float4*)s)[2 * j];
    const float4 v1 = ((const float4*)s)[2 * j + 1];
    float4 o0 = make_float4(tf32r(v0.x), tf32r(v1.x), tf32r(v0.y), tf32r(v1.y));
    float4 o1 = make_float4(tf32r(v0.z), tf32r(v1.z), tf32r(v0.w), tf32r(v1.w));
    ((float4*)d)[2 * j] = o0;
    ((float4*)d)[2 * j + 1] = o1;
}

// ===========================================================================
// tf32 warp-MMA NT GEMM, big tile: block 128x256x32, warp tile 64x64,
// 8 warps, 1 CTA/SM, 3-stage cp.async, LDS.64 fragment loads (k-permuted).
// C[m,n] = sum_k A[m,k]*B[n,k].
// ===========================================================================
#define BM 128
#define BN 256
#define BK 32
#define PITCH 40                                  // floats/row (conflict-free LDS.64)
#define A_STAGE (128 * PITCH)                     // 5120 floats
#define B_STAGE (256 * PITCH)                     // 10240 floats
#define STAGE_FLOATS (A_STAGE + B_STAGE)          // 15360
#define NSTAGE 3
#define GEMM_SMEM (NSTAGE * STAGE_FLOATS * 4)     // 184320 B

template <bool ROUND_OUT>
__global__ __launch_bounds__(256, 1) void gemm_tc(const float* __restrict__ A,
                                                  const float* __restrict__ B,
                                                  float* __restrict__ C,
                                                  int Ndim, int Kdim) {
    extern __shared__ __align__(16) float sm[];
    const uint32_t sbase = smem_u32(sm);

    const int tid  = threadIdx.x;
    const int wid  = tid >> 5;
    const int lane = tid & 31;
    const int g    = lane >> 2;
    const int tg   = lane & 3;
    const int m0   = blockIdx.y * BM;
    const int n0   = blockIdx.x * BN;
    const int wm   = wid & 1;            // m half (64 rows)
    const int wn   = wid >> 1;           // n quarter (64 cols)

    // Staging: A row = tid>>1 (0..127), 4 float4s; B row = tid (0..255), 8 float4s.
    const int  ar  = tid >> 1;
    const int  af4 = (tid & 1) * 4;
    const float* ApG = A + (size_t)(m0 + ar) * Kdim + af4 * 4;
    const float* BpG = B + (size_t)(n0 + tid) * Kdim;
    const uint32_t sA = sbase + (ar * PITCH + af4 * 4) * 4;
    const uint32_t sB = sbase + (A_STAGE + tid * PITCH) * 4;

    float c[4][8][4];
#pragma unroll
    for (int mt = 0; mt < 4; mt++)
#pragma unroll
        for (int nt = 0; nt < 8; nt++)
#pragma unroll
            for (int i = 0; i < 4; i++) c[mt][nt][i] = 0.f;

    const int NK = Kdim / BK;

    auto stage_load = [&](int kt, int s) {
        const int kc = kt * BK;
        const uint32_t off = (uint32_t)s * STAGE_FLOATS * 4;
#pragma unroll
        for (int u = 0; u < 4; u++)
            cp_async16(sA + off + u * 16, ApG + kc + u * 4);
#pragma unroll
        for (int u = 0; u < 8; u++)
            cp_async16(sB + off + u * 16, BpG + kc + u * 4);
        CP_COMMIT();
    };

    stage_load(0, 0);
    if (NK > 1) stage_load(1, 1);
    else CP_COMMIT();   // keep group count consistent (never taken: NK>=32)

    for (int kt = 0; kt < NK; kt++) {
        if (kt < NK - 1) CP_WAIT1(); else CP_WAIT0();
        __syncthreads();            // stage kt landed; all past stage kt-1

        if (kt + 2 < NK) {
            int s = kt + 2; s -= (s / 3) * 3;    // (kt+2) % 3
            stage_load(kt + 2, s);
        }

        int cs = kt; cs -= (cs / 3) * 3;
        const float* Ab = sm + cs * STAGE_FLOATS;
        const float* Bb = Ab + A_STAGE;

#pragma unroll
        for (int ks = 0; ks < 4; ks++) {
            const int ko = ks * 8 + 2 * tg;      // permuted: float2 = (k=kc+tg, k=kc+tg+4)
            uint32_t af[4][4];
#pragma unroll
            for (int mt = 0; mt < 4; mt++) {
                const int r = wm * 64 + mt * 16 + g;
                const float2 p0 = *(const float2*)(Ab + r * PITCH + ko);
                const float2 p1 = *(const float2*)(Ab + (r + 8) * PITCH + ko);
                af[mt][0] = __float_as_uint(p0.x);
                af[mt][1] = __float_as_uint(p1.x);
                af[mt][2] = __float_as_uint(p0.y);
                af[mt][3] = __float_as_uint(p1.y);
            }
#pragma unroll
            for (int nt = 0; nt < 8; nt++) {
                const int n = wn * 64 + nt * 8 + g;
                const float2 q = *(const float2*)(Bb + n * PITCH + ko);
                uint32_t bf[2] = {__float_as_uint(q.x), __float_as_uint(q.y)};
#pragma unroll
                for (int mt = 0; mt < 4; mt++)
                    mma_tf32(c[mt][nt], af[mt], bf);
            }
        }
    }

    // Epilogue (natural column order)
#pragma unroll
    for (int mt = 0; mt < 4; mt++) {
        const int row = m0 + wm * 64 + mt * 16 + g;
#pragma unroll
        for (int nt = 0; nt < 8; nt++) {
            const int col = n0 + wn * 64 + nt * 8 + 2 * tg;
            float v0 = c[mt][nt][0], v1 = c[mt][nt][1];
            float v2 = c[mt][nt][2], v3 = c[mt][nt][3];
            if (ROUND_OUT) { v0 = tf32r(v0); v1 = tf32r(v1); v2 = tf32r(v2); v3 = tf32r(v3); }
            *(float2*)(C + (size_t)row * Ndim + col)       = make_float2(v0, v1);
            *(float2*)(C + (size_t)(row + 8) * Ndim + col) = make_float2(v2, v3);
        }
    }
}

// ===========================================================================
// Sliding-window attention (round-6 proven version, unchanged).
// ===========================================================================
#define AQ 128
#define KP 68
#define VP 72
#define KCH (64 * KP)
#define VCH (64 * VP)
#define PSOFF (2 * KCH + 2 * VCH)
#define ATT_SMEM ((PSOFF + 128 * 68) * 4)   // 106496 B

__global__ __launch_bounds__(256) void attn_mma(const float* __restrict__ qkv,
                                                float* __restrict__ outp) {
    extern __shared__ __align__(16) float sm[];
    const uint32_t sbase = smem_u32(sm);
    float* Ps = sm + PSOFF;

    const int tid  = threadIdx.x;
    const int wid  = tid >> 5;
    const int lane = tid & 31;
    const int g    = lane >> 2;
    const int tg   = lane & 3;
    const int q0   = blockIdx.x * AQ;
    const int h    = blockIdx.y;
    const int b    = blockIdx.z;
    const int qw   = q0 + wid * 16;

    const float* base  = qkv + (size_t)b * T_ * E3_ + h * DH_;
    const float* baseK = base + D_;
    const float* baseV = base + 2 * D_;

    float qa[8][4];
    {
        const float* Qr0 = base + (size_t)(qw + g) * E3_;
        const float* Qr1 = base + (size_t)(qw + 8 + g) * E3_;
#pragma unroll
        for (int ks = 0; ks < 8; ks++) {
            qa[ks][0] = Qr0[ks * 8 + tg] * SCALE_;
            qa[ks][1] = Qr1[ks * 8 + tg] * SCALE_;
            qa[ks][2] = Qr0[ks * 8 + tg + 4] * SCALE_;
            qa[ks][3] = Qr1[ks * 8 + tg + 4] * SCALE_;
        }
    }

    float O[8][4];
#pragma unroll
    for (int nt = 0; nt < 8; nt++)
#pragma unroll
        for (int i = 0; i < 4; i++) O[nt][i] = 0.f;
    float mrow[2] = {-1e30f, -1e30f};
    float lrow[2] = {0.f, 0.f};

    const int c_lo = (q0 > 255 ? q0 - 255 : 0) >> 6;
    const int c_hi = (q0 + AQ - 1) >> 6;

    const int ldr = tid >> 4;
    const int ldf = tid & 15;

    auto issue = [&](int c, int s) {
        const int k0 = c << 6;
        const uint32_t kb = sbase + (uint32_t)s * KCH * 4;
        const uint32_t vb = sbase + (2 * KCH + (uint32_t)s * VCH) * 4;
#pragma unroll
        for (int u = 0; u < 4; u++) {
            const int r = ldr + u * 16;
            cp_async16(kb + (r * KP + ldf * 4) * 4, baseK + (size_t)(k0 + r) * E3_ + ldf * 4);
            cp_async16(vb + (r * VP + ldf * 4) * 4, baseV + (size_t)(k0 + r) * E3_ + ldf * 4);
        }
        CP_COMMIT();
    };

    issue(c_lo, 0);

    for (int c = c_lo; c <= c_hi; c++) {
        const int k0 = c << 6;
        const int st = (c - c_lo) & 1;
        CP_WAIT0();
        __syncthreads();
        if (c < c_hi) issue(c + 1, st ^ 1);

        const float* Kb = sm + st * KCH;
        const float* Vb = sm + 2 * KCH + st * VCH;

        const bool active = !(k0 > qw + 15 || k0 < qw - 318);
        if (active) {
            float s[8][4];
#pragma unroll
            for (int nt = 0; nt < 8; nt++)
#pragma unroll
                for (int i = 0; i < 4; i++) s[nt][i] = 0.f;

#pragma unroll
            for (int ks = 0; ks < 8; ks++) {
                uint32_t a[4] = {__float_as_uint(qa[ks][0]), __float_as_uint(qa[ks][1]),
                                 __float_as_uint(qa[ks][2]), __float_as_uint(qa[ks][3])};
#pragma unroll
                for (int nt = 0; nt < 8; nt++) {
                    const float* kp = &Kb[(nt * 8 + g) * KP + ks * 8 + tg];
                    uint32_t bfr[2] = {__float_as_uint(kp[0]), __float_as_uint(kp[4])};
                    mma_tf32(s[nt], a, bfr);
                }
            }

#pragma unroll
            for (int nt = 0; nt < 8; nt++) {
#pragma unroll
                for (int p = 0; p < 2; p++) {
#pragma unroll
                    for (int j = 0; j < 2; j++) {
                        const int qr = qw + g + 8 * p;
                        const int kc = k0 + nt * 8 + 2 * tg + j;
                        const int d  = qr - kc;
                        if (!(d >= 0 && d < WIN_)) s[nt][p * 2 + j] = -1e30f;
                    }
                }
            }

#pragma unroll
            for (int p = 0; p < 2; p++) {
                float mx = -1e30f;
#pragma unroll
                for (int nt = 0; nt < 8; nt++) {
                    mx = fmaxf(mx, s[nt][p * 2 + 0]);
                    mx = fmaxf(mx, s[nt][p * 2 + 1]);
                }
                mx = fmaxf(mx, __shfl_xor_sync(0xffffffffu, mx, 1));
                mx = fmaxf(mx, __shfl_xor_sync(0xffffffffu, mx, 2));
                const float mnew = fmaxf(mrow[p], mx);
                float sum = 0.f;
#pragma unroll
                for (int nt = 0; nt < 8; nt++) {
#pragma unroll
                    for (int j = 0; j < 2; j++) {
                        const float v = s[nt][p * 2 + j];
                        const float pv = (v < -5e29f) ? 0.f : __expf(v - mnew);
                        s[nt][p * 2 + j] = pv;
                        sum += pv;
                    }
                }
                sum += __shfl_xor_sync(0xffffffffu, sum, 1);
                sum += __shfl_xor_sync(0xffffffffu, sum, 2);
                const float alpha = (mrow[p] < -5e29f) ? 0.f : __expf(mrow[p] - mnew);
                lrow[p] = lrow[p] * alpha + sum;
                mrow[p] = mnew;
#pragma unroll
                for (int nt = 0; nt < 8; nt++) {
                    O[nt][p * 2 + 0] *= alpha;
                    O[nt][p * 2 + 1] *= alpha;
                }
            }

            const int pr0 = wid * 16 + g;
            const int pr1 = pr0 + 8;
#pragma unroll
            for (int nt = 0; nt < 8; nt++) {
                *(float2*)&Ps[pr0 * 68 + nt * 8 + 2 * tg] =
                    make_float2(tf32r(s[nt][0]), tf32r(s[nt][1]));
                *(float2*)&Ps[pr1 * 68 + nt * 8 + 2 * tg] =
                    make_float2(tf32r(s[nt][2]), tf32r(s[nt][3]));
            }
            __syncwarp();

#pragma unroll
            for (int ks = 0; ks < 8; ks++) {
                const float* pp0 = &Ps[pr0 * 68 + ks * 8 + tg];
                const float* pp1 = &Ps[pr1 * 68 + ks * 8 + tg];
                uint32_t a[4] = {__float_as_uint(pp0[0]), __float_as_uint(pp1[0]),
                                 __float_as_uint(pp0[4]), __float_as_uint(pp1[4])};
#pragma unroll
                for (int nt = 0; nt < 8; nt++) {
                    const float* vp = &Vb[(ks * 8 + tg) * VP + nt * 8 + g];
                    uint32_t bfr[2] = {__float_as_uint(vp[0]), __float_as_uint(vp[4 * VP])};
                    mma_tf32(O[nt], a, bfr);
                }
            }
        }
        __syncthreads();
    }

    const float inv0 = 1.0f / lrow[0];
    const float inv1 = 1.0f / lrow[1];
    const int row0 = b * T_ + qw + g;
    const int row1 = row0 + 8;
    const int j0 = 2 * tg, j1 = 2 * tg + 1;
    const int s0 = (j0 < 4) ? 2 * j0 : 2 * j0 - 7;
    const int s1 = (j1 < 4) ? 2 * j1 : 2 * j1 - 7;
#pragma unroll
    for (int nt = 0; nt < 8; nt++) {
        const int colb = h * DH_ + nt * 8;
        outp[(size_t)row0 * D_ + colb + s0] = tf32r(O[nt][0] * inv0);
        outp[(size_t)row0 * D_ + colb + s1] = tf32r(O[nt][1] * inv0);
        outp[(size_t)row1 * D_ + colb + s0] = tf32r(O[nt][2] * inv1);
        outp[(size_t)row1 * D_ + colb + s1] = tf32r(O[nt][3] * inv1);
    }
}

// ---------------------------------------------------------------------------
// Host launcher
// ---------------------------------------------------------------------------
extern "C" void kernel_launch(void* const* d_in, const int* in_sizes, int n_in,
                              void* d_out, int out_size) {
    (void)in_sizes; (void)n_in; (void)out_size;
    const float* x     = (const float*)d_in[0];   // [B,T,D]
    const float* w_qkv = (const float*)d_in[1];   // [3072,1024]
    const float* w_out = (const float*)d_in[2];   // [1024,1024]
    float* out = (float*)d_out;                   // [B,T,D]

    float *qkvbuf, *attbuf, *xr, *wqkvr, *woutr;
    cudaGetSymbolAddress((void**)&qkvbuf, g_qkv);
    cudaGetSymbolAddress((void**)&attbuf, g_att);
    cudaGetSymbolAddress((void**)&xr,     g_xr);
    cudaGetSymbolAddress((void**)&wqkvr,  g_wqkvr);
    cudaGetSymbolAddress((void**)&woutr,  g_woutr);

    cudaFuncSetAttribute(gemm_tc<true>,  cudaFuncAttributeMaxDynamicSharedMemorySize, GEMM_SMEM);
    cudaFuncSetAttribute(gemm_tc<false>, cudaFuncAttributeMaxDynamicSharedMemorySize, GEMM_SMEM);
    cudaFuncSetAttribute(attn_mma, cudaFuncAttributeMaxDynamicSharedMemorySize, ATT_SMEM);

    // 0) Fused pre-round + k-permute of all GEMM inputs (single launch)
    {
        const int total = NX8 + NW8 + NO8;    // 1048576
        preround_all<<<(total + 255) / 256, 256>>>(x, w_qkv, w_out, xr, wqkvr, woutr);
    }

    // 1) QKV projection (natural-layout tf32-rounded output for attention)
    gemm_tc<true><<<dim3(E3_ / BN, M_ / BM), 256, GEMM_SMEM>>>(xr, wqkvr, qkvbuf, E3_, D_);

    // 2) Sliding-window attention (writes k-permuted g_att)
    attn_mma<<<dim3(T_ / AQ, H_, B_), 256, ATT_SMEM>>>(qkvbuf, attbuf);

    // 3) Output projection (final fp32 output)
    gemm_tc<false><<<dim3(D_ / BN, M_ / BM), 256, GEMM_SMEM>>>(attbuf, woutr, out, D_, D_);
}

// round 8
// speedup vs baseline: 1.0160x; 1.0160x over previous
#include <cuda_runtime.h>
#include <cstdint>
#include <math.h>

// Problem constants
#define B_    2
#define T_    2048
#define D_    1024
#define H_    16
#define DH_   64
#define WIN_  256
#define E3_   3072          // 3*H*Dh
#define M_    (B_ * T_)     // 4096
#define SCALE_ 0.125f       // 64^-0.5

// Scratch (static device globals — allocation-free per harness rules)
__device__ float g_qkv[(size_t)M_ * E3_];     // [4096, 3072] natural, tf32-rounded
__device__ float g_att[(size_t)M_ * D_];      // [4096, 1024] 16-block k-PERMUTED
__device__ float g_xr[(size_t)M_ * D_];       // pre-rounded + 16-permuted x
__device__ float g_wqkvr[(size_t)E3_ * D_];   // pre-rounded + 16-permuted w_qkv
__device__ float g_woutr[(size_t)D_ * D_];    // pre-rounded + 16-permuted w_out

// ===========================================================================
// Helpers
// ===========================================================================
__device__ __forceinline__ uint32_t smem_u32(const void* p) {
    uint32_t a;
    asm("{ .reg .u64 t; cvta.to.shared.u64 t, %1; cvt.u32.u64 %0, t; }" : "=r"(a) : "l"(p));
    return a;
}
__device__ __forceinline__ void cp_async16(uint32_t saddr, const void* gptr) {
    asm volatile("cp.async.cg.shared.global [%0], [%1], 16;" :: "r"(saddr), "l"(gptr));
}
#define CP_COMMIT() asm volatile("cp.async.commit_group;" ::: "memory")
#define CP_WAIT0()  asm volatile("cp.async.wait_group 0;" ::: "memory")

__device__ __forceinline__ float tf32r(float f) {   // round-to-nearest onto tf32 grid
    uint32_t r;
    asm("cvt.rna.tf32.f32 %0, %1;" : "=r"(r) : "f"(f));
    return __uint_as_float(r);
}
__device__ __forceinline__ void mma_tf32(float* c, const uint32_t* a, const uint32_t* b) {
    asm volatile(
        "mma.sync.aligned.m16n8k8.row.col.f32.tf32.tf32.f32 "
        "{%0,%1,%2,%3}, {%4,%5,%6,%7}, {%8,%9}, {%0,%1,%2,%3};"
        : "+f"(c[0]), "+f"(c[1]), "+f"(c[2]), "+f"(c[3])
        : "r"(a[0]), "r"(a[1]), "r"(a[2]), "r"(a[3]), "r"(b[0]), "r"(b[1]));
}

// Fused pre-round + 16-block k-permute for all three GEMM operands.
// Within each 16-float k-block: dst[4t+i] = src[t+4i]  (t,i in 0..3).
// One LDS.128 at 4*tg then yields fragments {tg, tg+4, tg+8, tg+12}.
#define NX16 (M_ * D_ / 16)
#define NW16 (E3_ * D_ / 16)
#define NO16 (D_ * D_ / 16)
__global__ void preround_all(const float* __restrict__ x,  const float* __restrict__ wq,
                             const float* __restrict__ wo, float* __restrict__ xr,
                             float* __restrict__ wqr,      float* __restrict__ wor) {
    int i = blockIdx.x * blockDim.x + threadIdx.x;
    const float* s; float* d; int j;
    if (i < NX16)             { s = x;  d = xr;  j = i; }
    else if (i < NX16 + NW16) { s = wq; d = wqr; j = i - NX16; }
    else if (i < NX16 + NW16 + NO16) { s = wo; d = wor; j = i - NX16 - NW16; }
    else return;
    const float4 v0 = ((const float4*)s)[4 * j + 0];
    const float4 v1 = ((const float4*)s)[4 * j + 1];
    const float4 v2 = ((const float4*)s)[4 * j + 2];
    const float4 v3 = ((const float4*)s)[4 * j + 3];
    ((float4*)d)[4 * j + 0] = make_float4(tf32r(v0.x), tf32r(v1.x), tf32r(v2.x), tf32r(v3.x));
    ((float4*)d)[4 * j + 1] = make_float4(tf32r(v0.y), tf32r(v1.y), tf32r(v2.y), tf32r(v3.y));
    ((float4*)d)[4 * j + 2] = make_float4(tf32r(v0.z), tf32r(v1.z), tf32r(v2.z), tf32r(v3.z));
    ((float4*)d)[4 * j + 3] = make_float4(tf32r(v0.w), tf32r(v1.w), tf32r(v2.w), tf32r(v3.w));
}

// ===========================================================================
// tf32 warp-MMA NT GEMM on 16-permuted inputs. LDS.128 fragment loads
// (one load = two k-steps). Block 128x128x32, 8 warps, 64x32 warp tile,
// 2 CTA/SM, 2-stage cp.async, 1 barrier/iter.
// ===========================================================================
#define BM 128
#define BN 128
#define BK 32
#define PITCH 48                                   // 48 mod 32 = 16 -> phase-conflict-free LDS.128
#define A_STAGE (128 * PITCH)
#define STAGE_FLOATS (2 * 128 * PITCH)             // 12288 floats
#define GEMM_SMEM (2 * STAGE_FLOATS * 4)           // 98304 B

template <bool ROUND_OUT>
__global__ __launch_bounds__(256, 2) void gemm_tc(const float* __restrict__ A,
                                                  const float* __restrict__ B,
                                                  float* __restrict__ C,
                                                  int Ndim, int Kdim) {
    extern __shared__ __align__(16) float sm[];
    const uint32_t sbase = smem_u32(sm);

    const int tid  = threadIdx.x;
    const int wid  = tid >> 5;
    const int lane = tid & 31;
    const int g    = lane >> 2;
    const int tg   = lane & 3;
    const int m0   = blockIdx.y * BM;
    const int n0   = blockIdx.x * BN;
    const int wm   = wid & 1;
    const int wn   = wid >> 1;

    // Staging: row = tid>>1 (0..127), 4 float4 slots each for A and B
    const int ar  = tid >> 1;
    const int af4 = (tid & 1) * 4;
    const float* ApG = A + (size_t)(m0 + ar) * Kdim + af4 * 4;
    const float* BpG = B + (size_t)(n0 + ar) * Kdim + af4 * 4;
    const uint32_t sA = sbase + (ar * PITCH + af4 * 4) * 4;
    const uint32_t sB = sbase + (A_STAGE + ar * PITCH + af4 * 4) * 4;

    float c[4][4][4];
#pragma unroll
    for (int mt = 0; mt < 4; mt++)
#pragma unroll
        for (int nt = 0; nt < 4; nt++)
#pragma unroll
            for (int i = 0; i < 4; i++) c[mt][nt][i] = 0.f;

    const int NK = Kdim / BK;

    // Prologue: stage 0
    {
#pragma unroll
        for (int u = 0; u < 4; u++) {
            cp_async16(sA + u * 16, ApG + u * 4);
            cp_async16(sB + u * 16, BpG + u * 4);
        }
        CP_COMMIT();
    }

    for (int kt = 0; kt < NK; kt++) {
        CP_WAIT0();
        __syncthreads();          // tile kt landed; everyone past tile kt-1

        if (kt + 1 < NK) {        // overlap: stage kt+1 while computing kt
            const uint32_t off = (uint32_t)((kt + 1) & 1) * STAGE_FLOATS * 4;
            const int kc = (kt + 1) * BK;
#pragma unroll
            for (int u = 0; u < 4; u++) {
                cp_async16(sA + off + u * 16, ApG + kc + u * 4);
                cp_async16(sB + off + u * 16, BpG + kc + u * 4);
            }
            CP_COMMIT();
        }

        const float* Ab = sm + (kt & 1) * STAGE_FLOATS;
        const float* Bb = Ab + A_STAGE;

#pragma unroll
        for (int kp = 0; kp < 2; kp++) {            // k-pair: covers ks=2kp, 2kp+1
            const int ko = kp * 16 + 4 * tg;        // float4 -> frags {tg,tg+4,tg+8,tg+12}
            float4 bq[4];
#pragma unroll
            for (int nt = 0; nt < 4; nt++)
                bq[nt] = *(const float4*)(Bb + (wn * 32 + nt * 8 + g) * PITCH + ko);
#pragma unroll
            for (int mt = 0; mt < 4; mt++) {
                const int r = wm * 64 + mt * 16 + g;
                const float4 aL = *(const float4*)(Ab + r * PITCH + ko);
                const float4 aH = *(const float4*)(Ab + (r + 8) * PITCH + ko);
                const uint32_t ae[4] = {__float_as_uint(aL.x), __float_as_uint(aH.x),
                                        __float_as_uint(aL.y), __float_as_uint(aH.y)};
                const uint32_t ao[4] = {__float_as_uint(aL.z), __float_as_uint(aH.z),
                                        __float_as_uint(aL.w), __float_as_uint(aH.w)};
#pragma unroll
                for (int nt = 0; nt < 4; nt++) {
                    const uint32_t be[2] = {__float_as_uint(bq[nt].x), __float_as_uint(bq[nt].y)};
                    mma_tf32(c[mt][nt], ae, be);
                    const uint32_t bo[2] = {__float_as_uint(bq[nt].z), __float_as_uint(bq[nt].w)};
                    mma_tf32(c[mt][nt], ao, bo);
                }
            }
        }
    }

    // Epilogue (natural column order)
#pragma unroll
    for (int mt = 0; mt < 4; mt++) {
        const int row = m0 + wm * 64 + mt * 16 + g;
#pragma unroll
        for (int nt = 0; nt < 4; nt++) {
            const int col = n0 + wn * 32 + nt * 8 + 2 * tg;
            float v0 = c[mt][nt][0], v1 = c[mt][nt][1];
            float v2 = c[mt][nt][2], v3 = c[mt][nt][3];
            if (ROUND_OUT) { v0 = tf32r(v0); v1 = tf32r(v1); v2 = tf32r(v2); v3 = tf32r(v3); }
            *(float2*)(C + (size_t)row * Ndim + col)       = make_float2(v0, v1);
            *(float2*)(C + (size_t)(row + 8) * Ndim + col) = make_float2(v2, v3);
        }
    }
}

// ===========================================================================
// Sliding-window attention (round-6 proven version; epilogue now stores
// g_att in the 16-block permutation expected by gemm2).
// ===========================================================================
#define AQ 128
#define KP 68
#define VP 72
#define KCH (64 * KP)
#define VCH (64 * VP)
#define PSOFF (2 * KCH + 2 * VCH)
#define ATT_SMEM ((PSOFF + 128 * 68) * 4)   // 106496 B

__global__ __launch_bounds__(256) void attn_mma(const float* __restrict__ qkv,
                                                float* __restrict__ outp) {
    extern __shared__ __align__(16) float sm[];
    const uint32_t sbase = smem_u32(sm);
    float* Ps = sm + PSOFF;

    const int tid  = threadIdx.x;
    const int wid  = tid >> 5;
    const int lane = tid & 31;
    const int g    = lane >> 2;
    const int tg   = lane & 3;
    const int q0   = blockIdx.x * AQ;
    const int h    = blockIdx.y;
    const int b    = blockIdx.z;
    const int qw   = q0 + wid * 16;

    const float* base  = qkv + (size_t)b * T_ * E3_ + h * DH_;
    const float* baseK = base + D_;
    const float* baseV = base + 2 * D_;

    float qa[8][4];
    {
        const float* Qr0 = base + (size_t)(qw + g) * E3_;
        const float* Qr1 = base + (size_t)(qw + 8 + g) * E3_;
#pragma unroll
        for (int ks = 0; ks < 8; ks++) {
            qa[ks][0] = Qr0[ks * 8 + tg] * SCALE_;
            qa[ks][1] = Qr1[ks * 8 + tg] * SCALE_;
            qa[ks][2] = Qr0[ks * 8 + tg + 4] * SCALE_;
            qa[ks][3] = Qr1[ks * 8 + tg + 4] * SCALE_;
        }
    }

    float O[8][4];
#pragma unroll
    for (int nt = 0; nt < 8; nt++)
#pragma unroll
        for (int i = 0; i < 4; i++) O[nt][i] = 0.f;
    float mrow[2] = {-1e30f, -1e30f};
    float lrow[2] = {0.f, 0.f};

    const int c_lo = (q0 > 255 ? q0 - 255 : 0) >> 6;
    const int c_hi = (q0 + AQ - 1) >> 6;

    const int ldr = tid >> 4;
    const int ldf = tid & 15;

    auto issue = [&](int c, int s) {
        const int k0 = c << 6;
        const uint32_t kb = sbase + (uint32_t)s * KCH * 4;
        const uint32_t vb = sbase + (2 * KCH + (uint32_t)s * VCH) * 4;
#pragma unroll
        for (int u = 0; u < 4; u++) {
            const int r = ldr + u * 16;
            cp_async16(kb + (r * KP + ldf * 4) * 4, baseK + (size_t)(k0 + r) * E3_ + ldf * 4);
            cp_async16(vb + (r * VP + ldf * 4) * 4, baseV + (size_t)(k0 + r) * E3_ + ldf * 4);
        }
        CP_COMMIT();
    };

    issue(c_lo, 0);

    for (int c = c_lo; c <= c_hi; c++) {
        const int k0 = c << 6;
        const int st = (c - c_lo) & 1;
        CP_WAIT0();
        __syncthreads();
        if (c < c_hi) issue(c + 1, st ^ 1);

        const float* Kb = sm + st * KCH;
        const float* Vb = sm + 2 * KCH + st * VCH;

        const bool active = !(k0 > qw + 15 || k0 < qw - 318);
        if (active) {
            float s[8][4];
#pragma unroll
            for (int nt = 0; nt < 8; nt++)
#pragma unroll
                for (int i = 0; i < 4; i++) s[nt][i] = 0.f;

#pragma unroll
            for (int ks = 0; ks < 8; ks++) {
                uint32_t a[4] = {__float_as_uint(qa[ks][0]), __float_as_uint(qa[ks][1]),
                                 __float_as_uint(qa[ks][2]), __float_as_uint(qa[ks][3])};
#pragma unroll
                for (int nt = 0; nt < 8; nt++) {
                    const float* kp = &Kb[(nt * 8 + g) * KP + ks * 8 + tg];
                    uint32_t bfr[2] = {__float_as_uint(kp[0]), __float_as_uint(kp[4])};
                    mma_tf32(s[nt], a, bfr);
                }
            }

#pragma unroll
            for (int nt = 0; nt < 8; nt++) {
#pragma unroll
                for (int p = 0; p < 2; p++) {
#pragma unroll
                    for (int j = 0; j < 2; j++) {
                        const int qr = qw + g + 8 * p;
                        const int kc = k0 + nt * 8 + 2 * tg + j;
                        const int d  = qr - kc;
                        if (!(d >= 0 && d < WIN_)) s[nt][p * 2 + j] = -1e30f;
                    }
                }
            }

#pragma unroll
            for (int p = 0; p < 2; p++) {
                float mx = -1e30f;
#pragma unroll
                for (int nt = 0; nt < 8; nt++) {
                    mx = fmaxf(mx, s[nt][p * 2 + 0]);
                    mx = fmaxf(mx, s[nt][p * 2 + 1]);
                }
                mx = fmaxf(mx, __shfl_xor_sync(0xffffffffu, mx, 1));
                mx = fmaxf(mx, __shfl_xor_sync(0xffffffffu, mx, 2));
                const float mnew = fmaxf(mrow[p], mx);
                float sum = 0.f;
#pragma unroll
                for (int nt = 0; nt < 8; nt++) {
#pragma unroll
                    for (int j = 0; j < 2; j++) {
                        const float v = s[nt][p * 2 + j];
                        const float pv = (v < -5e29f) ? 0.f : __expf(v - mnew);
                        s[nt][p * 2 + j] = pv;
                        sum += pv;
                    }
                }
                sum += __shfl_xor_sync(0xffffffffu, sum, 1);
                sum += __shfl_xor_sync(0xffffffffu, sum, 2);
                const float alpha = (mrow[p] < -5e29f) ? 0.f : __expf(mrow[p] - mnew);
                lrow[p] = lrow[p] * alpha + sum;
                mrow[p] = mnew;
#pragma unroll
                for (int nt = 0; nt < 8; nt++) {
                    O[nt][p * 2 + 0] *= alpha;
                    O[nt][p * 2 + 1] *= alpha;
                }
            }

            const int pr0 = wid * 16 + g;
            const int pr1 = pr0 + 8;
#pragma unroll
            for (int nt = 0; nt < 8; nt++) {
                *(float2*)&Ps[pr0 * 68 + nt * 8 + 2 * tg] =
                    make_float2(tf32r(s[nt][0]), tf32r(s[nt][1]));
                *(float2*)&Ps[pr1 * 68 + nt * 8 + 2 * tg] =
                    make_float2(tf32r(s[nt][2]), tf32r(s[nt][3]));
            }
            __syncwarp();

#pragma unroll
            for (int ks = 0; ks < 8; ks++) {
                const float* pp0 = &Ps[pr0 * 68 + ks * 8 + tg];
                const float* pp1 = &Ps[pr1 * 68 + ks * 8 + tg];
                uint32_t a[4] = {__float_as_uint(pp0[0]), __float_as_uint(pp1[0]),
                                 __float_as_uint(pp0[4]), __float_as_uint(pp1[4])};
#pragma unroll
                for (int nt = 0; nt < 8; nt++) {
                    const float* vp = &Vb[(ks * 8 + tg) * VP + nt * 8 + g];
                    uint32_t bfr[2] = {__float_as_uint(vp[0]), __float_as_uint(vp[4 * VP])};
                    mma_tf32(O[nt], a, bfr);
                }
            }
        }
        __syncthreads();
    }

    // Epilogue: normalize, tf32-round, store with 16-block permutation:
    // logical col-in-16 kk -> physical 4*(kk&3) + (kk>>2)
    const float inv0 = 1.0f / lrow[0];
    const float inv1 = 1.0f / lrow[1];
    const int row0 = b * T_ + qw + g;
    const int row1 = row0 + 8;
#pragma unroll
    for (int nt = 0; nt < 8; nt++) {
        const int kk0 = (nt & 1) * 8 + 2 * tg;
        const int kk1 = kk0 + 1;
        const int p0 = 4 * (kk0 & 3) + (kk0 >> 2);
        const int p1 = 4 * (kk1 & 3) + (kk1 >> 2);
        const int colb = h * DH_ + (nt >> 1) * 16;
        outp[(size_t)row0 * D_ + colb + p0] = tf32r(O[nt][0] * inv0);
        outp[(size_t)row0 * D_ + colb + p1] = tf32r(O[nt][1] * inv0);
        outp[(size_t)row1 * D_ + colb + p0] = tf32r(O[nt][2] * inv1);
        outp[(size_t)row1 * D_ + colb + p1] = tf32r(O[nt][3] * inv1);
    }
}

// ---------------------------------------------------------------------------
// Host launcher
// ---------------------------------------------------------------------------
extern "C" void kernel_launch(void* const* d_in, const int* in_sizes, int n_in,
                              void* d_out, int out_size) {
    (void)in_sizes; (void)n_in; (void)out_size;
    const float* x     = (const float*)d_in[0];   // [B,T,D]
    const float* w_qkv = (const float*)d_in[1];   // [3072,1024]
    const float* w_out = (const float*)d_in[2];   // [1024,1024]
    float* out = (float*)d_out;                   // [B,T,D]

    float *qkvbuf, *attbuf, *xr, *wqkvr, *woutr;
    cudaGetSymbolAddress((void**)&qkvbuf, g_qkv);
    cudaGetSymbolAddress((void**)&attbuf, g_att);
    cudaGetSymbolAddress((void**)&xr,     g_xr);
    cudaGetSymbolAddress((void**)&wqkvr,  g_wqkvr);
    cudaGetSymbolAddress((void**)&woutr,  g_woutr);

    cudaFuncSetAttribute(gemm_tc<true>,  cudaFuncAttributeMaxDynamicSharedMemorySize, GEMM_SMEM);
    cudaFuncSetAttribute(gemm_tc<false>, cudaFuncAttributeMaxDynamicSharedMemorySize, GEMM_SMEM);
    cudaFuncSetAttribute(attn_mma, cudaFuncAttributeMaxDynamicSharedMemorySize, ATT_SMEM);

    // 0) Fused pre-round + 16-block k-permute of all GEMM inputs
    {
        const int total = NX16 + NW16 + NO16;    // 524288
        preround_all<<<(total + 255) / 256, 256>>>(x, w_qkv, w_out, xr, wqkvr, woutr);
    }

    // 1) QKV projection (natural-layout tf32-rounded output for attention)
    gemm_tc<true><<<dim3(E3_ / BN, M_ / BM), 256, GEMM_SMEM>>>(xr, wqkvr, qkvbuf, E3_, D_);

    // 2) Sliding-window attention (writes 16-permuted g_att)
    attn_mma<<<dim3(T_ / AQ, H_, B_), 256, ATT_SMEM>>>(qkvbuf, attbuf);

    // 3) Output projection (final fp32 output)
    gemm_tc<false><<<dim3(D_ / BN, M_ / BM), 256, GEMM_SMEM>>>(attbuf, woutr, out, D_, D_);
}

// round 9
// speedup vs baseline: 1.6040x; 1.5787x over previous
#include <cuda_runtime.h>
#include <cstdint>
#include <math.h>

// Problem constants
#define B_    2
#define T_    2048
#define D_    1024
#define H_    16
#define DH_   64
#define WIN_  256
#define E3_   3072          // 3*H*Dh
#define M_    (B_ * T_)     // 4096
#define SCALE_ 0.125f       // 64^-0.5

// Scratch (static device globals — allocation-free per harness rules)
__device__ float g_qkv[(size_t)M_ * E3_];     // [4096, 3072] natural, tf32-rounded
__device__ float g_att[(size_t)M_ * D_];      // [4096, 1024] k-PERMUTED (8-group)
__device__ float g_xr[(size_t)M_ * D_];       // pre-rounded + k-permuted x
__device__ float g_wqkvr[(size_t)E3_ * D_];   // pre-rounded + k-permuted w_qkv
__device__ float g_woutr[(size_t)D_ * D_];    // pre-rounded + k-permuted w_out

// ===========================================================================
// Helpers
// ===========================================================================
__device__ __forceinline__ uint32_t smem_u32(const void* p) {
    uint32_t a;
    asm("{ .reg .u64 t; cvta.to.shared.u64 t, %1; cvt.u32.u64 %0, t; }" : "=r"(a) : "l"(p));
    return a;
}
__device__ __forceinline__ void cp_async16(uint32_t saddr, const void* gptr) {
    asm volatile("cp.async.cg.shared.global [%0], [%1], 16;" :: "r"(saddr), "l"(gptr));
}
#define CP_COMMIT() asm volatile("cp.async.commit_group;" ::: "memory")
#define CP_WAIT0()  asm volatile("cp.async.wait_group 0;" ::: "memory")

__device__ __forceinline__ float tf32r(float f) {   // round-to-nearest onto tf32 grid
    uint32_t r;
    asm("cvt.rna.tf32.f32 %0, %1;" : "=r"(r) : "f"(f));
    return __uint_as_float(r);
}
__device__ __forceinline__ void mma_tf32(float* c, const uint32_t* a, const uint32_t* b) {
    asm volatile(
        "mma.sync.aligned.m16n8k8.row.col.f32.tf32.tf32.f32 "
        "{%0,%1,%2,%3}, {%4,%5,%6,%7}, {%8,%9}, {%0,%1,%2,%3};"
        : "+f"(c[0]), "+f"(c[1]), "+f"(c[2]), "+f"(c[3])
        : "r"(a[0]), "r"(a[1]), "r"(a[2]), "r"(a[3]), "r"(b[0]), "r"(b[1]));
}

// Fused pre-round + 8-group k-permute for all three GEMM operands (1 launch).
// Permutes each 8-float k-group to [a0,a4,a1,a5,a2,a6,a3,a7] so fragment
// pairs (k, k+4) are contiguous (LDS.64 in the GEMM).
#define NX8 (M_ * D_ / 8)
#define NW8 (E3_ * D_ / 8)
#define NO8 (D_ * D_ / 8)
__global__ void preround_all(const float* __restrict__ x,  const float* __restrict__ wq,
                             const float* __restrict__ wo, float* __restrict__ xr,
                             float* __restrict__ wqr,      float* __restrict__ wor) {
    int i = blockIdx.x * blockDim.x + threadIdx.x;
    const float* s; float* d; int j;
    if (i < NX8)            { s = x;  d = xr;  j = i; }
    else if (i < NX8 + NW8) { s = wq; d = wqr; j = i - NX8; }
    else if (i < NX8 + NW8 + NO8) { s = wo; d = wor; j = i - NX8 - NW8; }
    else return;
    const float4 v0 = ((const float4*)s)[2 * j];
    const float4 v1 = ((const float4*)s)[2 * j + 1];
    float4 o0 = make_float4(tf32r(v0.x), tf32r(v1.x), tf32r(v0.y), tf32r(v1.y));
    float4 o1 = make_float4(tf32r(v0.z), tf32r(v1.z), tf32r(v0.w), tf32r(v1.w));
    ((float4*)d)[2 * j] = o0;
    ((float4*)d)[2 * j + 1] = o1;
}

// ===========================================================================
// tf32 warp-MMA NT GEMM on k-permuted inputs (ROUND-6 PROVEN VERSION).
// LDS.64 fragment loads. Block 128x128x32, 8 warps, 64x32 warp tile,
// 2 CTA/SM, 2-stage cp.async pipeline, 1 barrier/iter.
// ===========================================================================
#define BM 128
#define BN 128
#define BK 32
#define PITCH 40                                   // floats/row: conflict-free LDS.64
#define STAGE_FLOATS (2 * 128 * PITCH)             // A tile then B tile
#define GEMM_SMEM (2 * STAGE_FLOATS * 4)           // 81920 B

template <bool ROUND_OUT>
__global__ __launch_bounds__(256, 2) void gemm_tc(const float* __restrict__ A,
                                                  const float* __restrict__ B,
                                                  float* __restrict__ C,
                                                  int Ndim, int Kdim) {
    extern __shared__ __align__(16) float sm[];
    const uint32_t sbase = smem_u32(sm);

    const int tid  = threadIdx.x;
    const int wid  = tid >> 5;
    const int lane = tid & 31;
    const int g    = lane >> 2;
    const int tg   = lane & 3;
    const int m0   = blockIdx.y * BM;
    const int n0   = blockIdx.x * BN;
    const int wm   = wid & 1;
    const int wn   = wid >> 1;

    const int lr = tid >> 3;     // staging row 0..31 (x4 via +32 offsets)
    const int lf = tid & 7;      // float4 slot within 32-float k-row

    const uint32_t sa0 = sbase + (lr * PITCH + lf * 4) * 4;
    const uint32_t sb0 = sa0 + 128 * PITCH * 4;
    const float* Ap0 = A + (size_t)(m0 + lr) * Kdim + lf * 4;
    const float* Bp0 = B + (size_t)(n0 + lr) * Kdim + lf * 4;

    float c[4][4][4];
#pragma unroll
    for (int mt = 0; mt < 4; mt++)
#pragma unroll
        for (int nt = 0; nt < 4; nt++)
#pragma unroll
            for (int i = 0; i < 4; i++) c[mt][nt][i] = 0.f;

    const int NK = Kdim / BK;

    // Prologue: stage 0
    {
#pragma unroll
        for (int u = 0; u < 4; u++) {
            cp_async16(sa0 + u * 32 * PITCH * 4, Ap0 + (size_t)u * 32 * Kdim);
            cp_async16(sb0 + u * 32 * PITCH * 4, Bp0 + (size_t)u * 32 * Kdim);
        }
        CP_COMMIT();
    }

    for (int kt = 0; kt < NK; kt++) {
        CP_WAIT0();
        __syncthreads();          // tile kt landed; everyone past tile kt-1

        if (kt + 1 < NK) {        // overlap: stage kt+1 while computing kt
            const uint32_t off = (uint32_t)((kt + 1) & 1) * STAGE_FLOATS * 4;
            const int kc = (kt + 1) * BK;
#pragma unroll
            for (int u = 0; u < 4; u++) {
                cp_async16(sa0 + off + u * 32 * PITCH * 4, Ap0 + kc + (size_t)u * 32 * Kdim);
                cp_async16(sb0 + off + u * 32 * PITCH * 4, Bp0 + kc + (size_t)u * 32 * Kdim);
            }
            CP_COMMIT();
        }

        const float* Ab = sm + (kt & 1) * STAGE_FLOATS;
        const float* Bb = Ab + 128 * PITCH;

#pragma unroll
        for (int ks = 0; ks < 4; ks++) {
            const int ko = ks * 8 + 2 * tg;        // permuted: float2 = (k=kc+tg, k=kc+tg+4)
            uint32_t af[4][4], bf[4][2];
#pragma unroll
            for (int mt = 0; mt < 4; mt++) {
                const int r = wm * 64 + mt * 16 + g;
                const float2 p0 = *(const float2*)(Ab + r * PITCH + ko);
                const float2 p1 = *(const float2*)(Ab + (r + 8) * PITCH + ko);
                af[mt][0] = __float_as_uint(p0.x);
                af[mt][1] = __float_as_uint(p1.x);
                af[mt][2] = __float_as_uint(p0.y);
                af[mt][3] = __float_as_uint(p1.y);
            }
#pragma unroll
            for (int nt = 0; nt < 4; nt++) {
                const int n = wn * 32 + nt * 8 + g;
                const float2 q = *(const float2*)(Bb + n * PITCH + ko);
                bf[nt][0] = __float_as_uint(q.x);
                bf[nt][1] = __float_as_uint(q.y);
            }
#pragma unroll
            for (int mt = 0; mt < 4; mt++)
#pragma unroll
                for (int nt = 0; nt < 4; nt++)
                    mma_tf32(c[mt][nt], af[mt], bf[nt]);
        }
    }

    // Epilogue (natural column order)
#pragma unroll
    for (int mt = 0; mt < 4; mt++) {
        const int row = m0 + wm * 64 + mt * 16 + g;
#pragma unroll
        for (int nt = 0; nt < 4; nt++) {
            const int col = n0 + wn * 32 + nt * 8 + 2 * tg;
            float v0 = c[mt][nt][0], v1 = c[mt][nt][1];
            float v2 = c[mt][nt][2], v3 = c[mt][nt][3];
            if (ROUND_OUT) { v0 = tf32r(v0); v1 = tf32r(v1); v2 = tf32r(v2); v3 = tf32r(v3); }
            *(float2*)(C + (size_t)row * Ndim + col)       = make_float2(v0, v1);
            *(float2*)(C + (size_t)(row + 8) * Ndim + col) = make_float2(v2, v3);
        }
    }
}

// ===========================================================================
// Sliding-window attention (round-6 proven version) with 2 CTAs/SM forced
// via __launch_bounds__(256, 2). Epilogue stores g_att 8-group k-permuted.
// ===========================================================================
#define AQ 128
#define KP 68
#define VP 72
#define KCH (64 * KP)
#define VCH (64 * VP)
#define PSOFF (2 * KCH + 2 * VCH)
#define ATT_SMEM ((PSOFF + 128 * 68) * 4)   // 106496 B ; x2 CTAs = 212992 < 228KB

__global__ __launch_bounds__(256, 2) void attn_mma(const float* __restrict__ qkv,
                                                   float* __restrict__ outp) {
    extern __shared__ __align__(16) float sm[];
    const uint32_t sbase = smem_u32(sm);
    float* Ps = sm + PSOFF;

    const int tid  = threadIdx.x;
    const int wid  = tid >> 5;
    const int lane = tid & 31;
    const int g    = lane >> 2;
    const int tg   = lane & 3;
    const int q0   = blockIdx.x * AQ;
    const int h    = blockIdx.y;
    const int b    = blockIdx.z;
    const int qw   = q0 + wid * 16;

    const float* base  = qkv + (size_t)b * T_ * E3_ + h * DH_;
    const float* baseK = base + D_;
    const float* baseV = base + 2 * D_;

    float qa[8][4];
    {
        const float* Qr0 = base + (size_t)(qw + g) * E3_;
        const float* Qr1 = base + (size_t)(qw + 8 + g) * E3_;
#pragma unroll
        for (int ks = 0; ks < 8; ks++) {
            qa[ks][0] = Qr0[ks * 8 + tg] * SCALE_;
            qa[ks][1] = Qr1[ks * 8 + tg] * SCALE_;
            qa[ks][2] = Qr0[ks * 8 + tg + 4] * SCALE_;
            qa[ks][3] = Qr1[ks * 8 + tg + 4] * SCALE_;
        }
    }

    float O[8][4];
#pragma unroll
    for (int nt = 0; nt < 8; nt++)
#pragma unroll
        for (int i = 0; i < 4; i++) O[nt][i] = 0.f;
    float mrow[2] = {-1e30f, -1e30f};
    float lrow[2] = {0.f, 0.f};

    const int c_lo = (q0 > 255 ? q0 - 255 : 0) >> 6;
    const int c_hi = (q0 + AQ - 1) >> 6;

    const int ldr = tid >> 4;
    const int ldf = tid & 15;

    auto issue = [&](int c, int s) {
        const int k0 = c << 6;
        const uint32_t kb = sbase + (uint32_t)s * KCH * 4;
        const uint32_t vb = sbase + (2 * KCH + (uint32_t)s * VCH) * 4;
#pragma unroll
        for (int u = 0; u < 4; u++) {
            const int r = ldr + u * 16;
            cp_async16(kb + (r * KP + ldf * 4) * 4, baseK + (size_t)(k0 + r) * E3_ + ldf * 4);
            cp_async16(vb + (r * VP + ldf * 4) * 4, baseV + (size_t)(k0 + r) * E3_ + ldf * 4);
        }
        CP_COMMIT();
    };

    issue(c_lo, 0);

    for (int c = c_lo; c <= c_hi; c++) {
        const int k0 = c << 6;
        const int st = (c - c_lo) & 1;
        CP_WAIT0();
        __syncthreads();
        if (c < c_hi) issue(c + 1, st ^ 1);

        const float* Kb = sm + st * KCH;
        const float* Vb = sm + 2 * KCH + st * VCH;

        const bool active = !(k0 > qw + 15 || k0 < qw - 318);
        if (active) {
            float s[8][4];
#pragma unroll
            for (int nt = 0; nt < 8; nt++)
#pragma unroll
                for (int i = 0; i < 4; i++) s[nt][i] = 0.f;

#pragma unroll
            for (int ks = 0; ks < 8; ks++) {
                uint32_t a[4] = {__float_as_uint(qa[ks][0]), __float_as_uint(qa[ks][1]),
                                 __float_as_uint(qa[ks][2]), __float_as_uint(qa[ks][3])};
#pragma unroll
                for (int nt = 0; nt < 8; nt++) {
                    const float* kp = &Kb[(nt * 8 + g) * KP + ks * 8 + tg];
                    uint32_t bfr[2] = {__float_as_uint(kp[0]), __float_as_uint(kp[4])};
                    mma_tf32(s[nt], a, bfr);
                }
            }

#pragma unroll
            for (int nt = 0; nt < 8; nt++) {
#pragma unroll
                for (int p = 0; p < 2; p++) {
#pragma unroll
                    for (int j = 0; j < 2; j++) {
                        const int qr = qw + g + 8 * p;
                        const int kc = k0 + nt * 8 + 2 * tg + j;
                        const int d  = qr - kc;
                        if (!(d >= 0 && d < WIN_)) s[nt][p * 2 + j] = -1e30f;
                    }
                }
            }

#pragma unroll
            for (int p = 0; p < 2; p++) {
                float mx = -1e30f;
#pragma unroll
                for (int nt = 0; nt < 8; nt++) {
                    mx = fmaxf(mx, s[nt][p * 2 + 0]);
                    mx = fmaxf(mx, s[nt][p * 2 + 1]);
                }
                mx = fmaxf(mx, __shfl_xor_sync(0xffffffffu, mx, 1));
                mx = fmaxf(mx, __shfl_xor_sync(0xffffffffu, mx, 2));
                const float mnew = fmaxf(mrow[p], mx);
                float sum = 0.f;
#pragma unroll
                for (int nt = 0; nt < 8; nt++) {
#pragma unroll
                    for (int j = 0; j < 2; j++) {
                        const float v = s[nt][p * 2 + j];
                        const float pv = (v < -5e29f) ? 0.f : __expf(v - mnew);
                        s[nt][p * 2 + j] = pv;
                        sum += pv;
                    }
                }
                sum += __shfl_xor_sync(0xffffffffu, sum, 1);
                sum += __shfl_xor_sync(0xffffffffu, sum, 2);
                const float alpha = (mrow[p] < -5e29f) ? 0.f : __expf(mrow[p] - mnew);
                lrow[p] = lrow[p] * alpha + sum;
                mrow[p] = mnew;
#pragma unroll
                for (int nt = 0; nt < 8; nt++) {
                    O[nt][p * 2 + 0] *= alpha;
                    O[nt][p * 2 + 1] *= alpha;
                }
            }

            const int pr0 = wid * 16 + g;
            const int pr1 = pr0 + 8;
#pragma unroll
            for (int nt = 0; nt < 8; nt++) {
                *(float2*)&Ps[pr0 * 68 + nt * 8 + 2 * tg] =
                    make_float2(tf32r(s[nt][0]), tf32r(s[nt][1]));
                *(float2*)&Ps[pr1 * 68 + nt * 8 + 2 * tg] =
                    make_float2(tf32r(s[nt][2]), tf32r(s[nt][3]));
            }
            __syncwarp();

#pragma unroll
            for (int ks = 0; ks < 8; ks++) {
                const float* pp0 = &Ps[pr0 * 68 + ks * 8 + tg];
                const float* pp1 = &Ps[pr1 * 68 + ks * 8 + tg];
                uint32_t a[4] = {__float_as_uint(pp0[0]), __float_as_uint(pp1[0]),
                                 __float_as_uint(pp0[4]), __float_as_uint(pp1[4])};
#pragma unroll
                for (int nt = 0; nt < 8; nt++) {
                    const float* vp = &Vb[(ks * 8 + tg) * VP + nt * 8 + g];
                    uint32_t bfr[2] = {__float_as_uint(vp[0]), __float_as_uint(vp[4 * VP])};
                    mma_tf32(O[nt], a, bfr);
                }
            }
        }
        __syncthreads();
    }

    // Epilogue: normalize, tf32-round, store 8-group k-PERMUTED
    // (slot j<4 -> 2j, else 2j-7), matching preround_all's permutation.
    const float inv0 = 1.0f / lrow[0];
    const float inv1 = 1.0f / lrow[1];
    const int row0 = b * T_ + qw + g;
    const int row1 = row0 + 8;
    const int j0 = 2 * tg, j1 = 2 * tg + 1;
    const int s0 = (j0 < 4) ? 2 * j0 : 2 * j0 - 7;
    const int s1 = (j1 < 4) ? 2 * j1 : 2 * j1 - 7;
#pragma unroll
    for (int nt = 0; nt < 8; nt++) {
        const int colb = h * DH_ + nt * 8;
        outp[(size_t)row0 * D_ + colb + s0] = tf32r(O[nt][0] * inv0);
        outp[(size_t)row0 * D_ + colb + s1] = tf32r(O[nt][1] * inv0);
        outp[(size_t)row1 * D_ + colb + s0] = tf32r(O[nt][2] * inv1);
        outp[(size_t)row1 * D_ + colb + s1] = tf32r(O[nt][3] * inv1);
    }
}

// ---------------------------------------------------------------------------
// Host launcher
// ---------------------------------------------------------------------------
extern "C" void kernel_launch(void* const* d_in, const int* in_sizes, int n_in,
                              void* d_out, int out_size) {
    (void)in_sizes; (void)n_in; (void)out_size;
    const float* x     = (const float*)d_in[0];   // [B,T,D]
    const float* w_qkv = (const float*)d_in[1];   // [3072,1024]
    const float* w_out = (const float*)d_in[2];   // [1024,1024]
    float* out = (float*)d_out;                   // [B,T,D]

    float *qkvbuf, *attbuf, *xr, *wqkvr, *woutr;
    cudaGetSymbolAddress((void**)&qkvbuf, g_qkv);
    cudaGetSymbolAddress((void**)&attbuf, g_att);
    cudaGetSymbolAddress((void**)&xr,     g_xr);
    cudaGetSymbolAddress((void**)&wqkvr,  g_wqkvr);
    cudaGetSymbolAddress((void**)&woutr,  g_woutr);

    cudaFuncSetAttribute(gemm_tc<true>,  cudaFuncAttributeMaxDynamicSharedMemorySize, GEMM_SMEM);
    cudaFuncSetAttribute(gemm_tc<false>, cudaFuncAttributeMaxDynamicSharedMemorySize, GEMM_SMEM);
    cudaFuncSetAttribute(attn_mma, cudaFuncAttributeMaxDynamicSharedMemorySize, ATT_SMEM);

    // 0) Fused pre-round + 8-group k-permute of all GEMM inputs (1 launch)
    {
        const int total = NX8 + NW8 + NO8;    // 1048576
        preround_all<<<(total + 255) / 256, 256>>>(x, w_qkv, w_out, xr, wqkvr, woutr);
    }

    // 1) QKV projection (natural-layout tf32-rounded output for attention)
    gemm_tc<true><<<dim3(E3_ / BN, M_ / BM), 256, GEMM_SMEM>>>(xr, wqkvr, qkvbuf, E3_, D_);

    // 2) Sliding-window attention (writes 8-group-permuted g_att)
    attn_mma<<<dim3(T_ / AQ, H_, B_), 256, ATT_SMEM>>>(qkvbuf, attbuf);

    // 3) Output projection (final fp32 output)
    gemm_tc<false><<<dim3(D_ / BN, M_ / BM), 256, GEMM_SMEM>>>(attbuf, woutr, out, D_, D_);
}

// round 11
// speedup vs baseline: 2.2537x; 1.4050x over previous
#include <cuda_runtime.h>
#include <cuda_fp16.h>
#include <cstdint>
#include <math.h>

// Problem constants
#define B_    2
#define T_    2048
#define D_    1024
#define H_    16
#define DH_   64
#define WIN_  256
#define E3_   3072          // 3*H*Dh
#define M_    (B_ * T_)     // 4096
#define SCALE_ 0.125f       // 64^-0.5

// Scratch (static device globals — allocation-free per harness rules)
__device__ float  g_qkv[(size_t)M_ * E3_];     // [4096,3072] fp32, tf32-rounded
__device__ __half g_atth[(size_t)M_ * D_];     // [4096,1024] fp16, 16-permuted
__device__ __half g_xh[(size_t)M_ * D_];       // fp16 + 16-permuted x
__device__ __half g_wqh[(size_t)E3_ * D_];     // fp16 + 16-permuted w_qkv
__device__ __half g_woh[(size_t)D_ * D_];      // fp16 + 16-permuted w_out

// ===========================================================================
// Helpers
// ===========================================================================
__device__ __forceinline__ uint32_t smem_u32(const void* p) {
    uint32_t a;
    asm("{ .reg .u64 t; cvta.to.shared.u64 t, %1; cvt.u32.u64 %0, t; }" : "=r"(a) : "l"(p));
    return a;
}
__device__ __forceinline__ void cp_async16(uint32_t saddr, const void* gptr) {
    asm volatile("cp.async.cg.shared.global [%0], [%1], 16;" :: "r"(saddr), "l"(gptr));
}
#define CP_COMMIT() asm volatile("cp.async.commit_group;" ::: "memory")
#define CP_WAIT0()  asm volatile("cp.async.wait_group 0;" ::: "memory")

__device__ __forceinline__ float tf32r(float f) {
    uint32_t r;
    asm("cvt.rna.tf32.f32 %0, %1;" : "=r"(r) : "f"(f));
    return __uint_as_float(r);
}
// tf32 mma (attention only)
__device__ __forceinline__ void mma_tf32(float* c, const uint32_t* a, const uint32_t* b) {
    asm volatile(
        "mma.sync.aligned.m16n8k8.row.col.f32.tf32.tf32.f32 "
        "{%0,%1,%2,%3}, {%4,%5,%6,%7}, {%8,%9}, {%0,%1,%2,%3};"
        : "+f"(c[0]), "+f"(c[1]), "+f"(c[2]), "+f"(c[3])
        : "r"(a[0]), "r"(a[1]), "r"(a[2]), "r"(a[3]), "r"(b[0]), "r"(b[1]));
}
// fp16 mma (GEMMs): m16n8k16, fp32 accumulate
__device__ __forceinline__ void mma_f16(float* c, const uint32_t* a, const uint32_t* b) {
    asm volatile(
        "mma.sync.aligned.m16n8k16.row.col.f32.f16.f16.f32 "
        "{%0,%1,%2,%3}, {%4,%5,%6,%7}, {%8,%9}, {%0,%1,%2,%3};"
        : "+f"(c[0]), "+f"(c[1]), "+f"(c[2]), "+f"(c[3])
        : "r"(a[0]), "r"(a[1]), "r"(a[2]), "r"(a[3]), "r"(b[0]), "r"(b[1]));
}

// Fused fp32 -> fp16 convert + 16-group k-permute, all three operands.
// Within each 16 k-group: dst[4t+0..3] = src[2t, 2t+1, 2t+8, 2t+9].
#define NX16 (M_ * D_ / 16)
#define NW16 (E3_ * D_ / 16)
#define NO16 (D_ * D_ / 16)
__global__ void preround_all(const float* __restrict__ x,  const float* __restrict__ wq,
                             const float* __restrict__ wo, __half* __restrict__ xh,
                             __half* __restrict__ wqh,     __half* __restrict__ woh) {
    int i = blockIdx.x * blockDim.x + threadIdx.x;
    const float* s; __half* d; int j;
    if (i < NX16)             { s = x;  d = xh;  j = i; }
    else if (i < NX16 + NW16) { s = wq; d = wqh; j = i - NX16; }
    else if (i < NX16 + NW16 + NO16) { s = wo; d = woh; j = i - NX16 - NW16; }
    else return;
    const float4 v0 = ((const float4*)s)[4 * j + 0];   // src[0..3]
    const float4 v1 = ((const float4*)s)[4 * j + 1];   // src[4..7]
    const float4 v2 = ((const float4*)s)[4 * j + 2];   // src[8..11]
    const float4 v3 = ((const float4*)s)[4 * j + 3];   // src[12..15]
    __half2* o = (__half2*)(d + 16 * (size_t)j);
    o[0] = __floats2half2_rn(v0.x, v0.y);   // dst[0,1]   = src[0,1]
    o[1] = __floats2half2_rn(v2.x, v2.y);   // dst[2,3]   = src[8,9]
    o[2] = __floats2half2_rn(v0.z, v0.w);   // dst[4,5]   = src[2,3]
    o[3] = __floats2half2_rn(v2.z, v2.w);   // dst[6,7]   = src[10,11]
    o[4] = __floats2half2_rn(v1.x, v1.y);   // dst[8,9]   = src[4,5]
    o[5] = __floats2half2_rn(v3.x, v3.y);   // dst[10,11] = src[12,13]
    o[6] = __floats2half2_rn(v1.z, v1.w);   // dst[12,13] = src[6,7]
    o[7] = __floats2half2_rn(v3.z, v3.w);   // dst[14,15] = src[14,15]
}

// ===========================================================================
// fp16 warp-MMA NT GEMM on 16-permuted inputs. m16n8k16, LDS.64 fragment
// loads. Block 128x128x32, 8 warps, 64x32 warp tile, 2 CTA/SM, 2-stage
// cp.async. C[m,n] = sum_k A[m,k]*B[n,k], fp32 accumulate/output.
// Staging (FIXED): 4 x 16B chunks per 32-half row; lr=tid>>2 covers 64 rows
// per pass, 2 passes for 128 rows. No reads beyond kc+32.
// ===========================================================================
#define BM 128
#define BN 128
#define BK 32
#define PITCH 80                                   // halves/row (64 data+16 pad... 32 data+48 slack)
#define STAGE_HALVES (2 * 128 * PITCH)             // A tile then B tile = 20480 halves
#define GEMM_SMEM (2 * STAGE_HALVES * 2)           // 81920 B

template <bool ROUND_OUT>
__global__ __launch_bounds__(256, 2) void gemm_tc(const __half* __restrict__ A,
                                                  const __half* __restrict__ B,
                                                  float* __restrict__ C,
                                                  int Ndim, int Kdim) {
    extern __shared__ __align__(16) __half smh[];
    const uint32_t sbase = smem_u32(smh);

    const int tid  = threadIdx.x;
    const int wid  = tid >> 5;
    const int lane = tid & 31;
    const int g    = lane >> 2;
    const int tg   = lane & 3;
    const int m0   = blockIdx.y * BM;
    const int n0   = blockIdx.x * BN;
    const int wm   = wid & 1;
    const int wn   = wid >> 1;

    const int lr = tid >> 2;     // staging row 0..63 (x2 via +64 offset)
    const int lf = tid & 3;      // 16B chunk (8 halves) within 32-half k-row

    const uint32_t sa0 = sbase + (lr * PITCH + lf * 8) * 2;
    const uint32_t sb0 = sa0 + 128 * PITCH * 2;
    const __half* Ap0 = A + (size_t)(m0 + lr) * Kdim + lf * 8;
    const __half* Bp0 = B + (size_t)(n0 + lr) * Kdim + lf * 8;

    float c[4][4][4];
#pragma unroll
    for (int mt = 0; mt < 4; mt++)
#pragma unroll
        for (int nt = 0; nt < 4; nt++)
#pragma unroll
            for (int i = 0; i < 4; i++) c[mt][nt][i] = 0.f;

    const int NK = Kdim / BK;

    // Prologue: stage 0
    {
#pragma unroll
        for (int u = 0; u < 2; u++) {
            cp_async16(sa0 + u * 64 * PITCH * 2, Ap0 + (size_t)u * 64 * Kdim);
            cp_async16(sb0 + u * 64 * PITCH * 2, Bp0 + (size_t)u * 64 * Kdim);
        }
        CP_COMMIT();
    }

    for (int kt = 0; kt < NK; kt++) {
        CP_WAIT0();
        __syncthreads();          // tile kt landed; everyone past tile kt-1

        if (kt + 1 < NK) {        // overlap: stage kt+1 while computing kt
            const uint32_t off = (uint32_t)((kt + 1) & 1) * STAGE_HALVES * 2;
            const int kc = (kt + 1) * BK;
#pragma unroll
            for (int u = 0; u < 2; u++) {
                cp_async16(sa0 + off + u * 64 * PITCH * 2, Ap0 + kc + (size_t)u * 64 * Kdim);
                cp_async16(sb0 + off + u * 64 * PITCH * 2, Bp0 + kc + (size_t)u * 64 * Kdim);
            }
            CP_COMMIT();
        }

        const __half* Ab = smh + (kt & 1) * STAGE_HALVES;
        const __half* Bb = Ab + 128 * PITCH;

#pragma unroll
        for (int kp = 0; kp < 2; kp++) {            // two k16 steps per BK=32
            const int ko = kp * 16 + 4 * tg;        // permuted quad: k={2tg,2tg+1,2tg+8,2tg+9}
            uint32_t af[4][4], bf[4][2];
#pragma unroll
            for (int mt = 0; mt < 4; mt++) {
                const int r = wm * 64 + mt * 16 + g;
                const uint2 u0 = *(const uint2*)(Ab + r * PITCH + ko);
                const uint2 u1 = *(const uint2*)(Ab + (r + 8) * PITCH + ko);
                af[mt][0] = u0.x;   // row r,   k lo pair
                af[mt][1] = u1.x;   // row r+8, k lo pair
                af[mt][2] = u0.y;   // row r,   k hi pair
                af[mt][3] = u1.y;   // row r+8, k hi pair
            }
#pragma unroll
            for (int nt = 0; nt < 4; nt++) {
                const int n = wn * 32 + nt * 8 + g;
                const uint2 q = *(const uint2*)(Bb + n * PITCH + ko);
                bf[nt][0] = q.x;
                bf[nt][1] = q.y;
            }
#pragma unroll
            for (int mt = 0; mt < 4; mt++)
#pragma unroll
                for (int nt = 0; nt < 4; nt++)
                    mma_f16(c[mt][nt], af[mt], bf[nt]);
        }
    }

    // Epilogue (natural column order, fp32 out)
#pragma unroll
    for (int mt = 0; mt < 4; mt++) {
        const int row = m0 + wm * 64 + mt * 16 + g;
#pragma unroll
        for (int nt = 0; nt < 4; nt++) {
            const int col = n0 + wn * 32 + nt * 8 + 2 * tg;
            float v0 = c[mt][nt][0], v1 = c[mt][nt][1];
            float v2 = c[mt][nt][2], v3 = c[mt][nt][3];
            if (ROUND_OUT) { v0 = tf32r(v0); v1 = tf32r(v1); v2 = tf32r(v2); v3 = tf32r(v3); }
            *(float2*)(C + (size_t)row * Ndim + col)       = make_float2(v0, v1);
            *(float2*)(C + (size_t)(row + 8) * Ndim + col) = make_float2(v2, v3);
        }
    }
}

// ===========================================================================
// Sliding-window attention (round-9 proven tf32 version, 2 CTA/SM).
// Only the epilogue differs from round 9: emits fp16 g_att, 16-permuted.
// ===========================================================================
#define AQ 128
#define KP 68
#define VP 72
#define KCH (64 * KP)
#define VCH (64 * VP)
#define PSOFF (2 * KCH + 2 * VCH)
#define ATT_SMEM ((PSOFF + 128 * 68) * 4)   // 106496 B ; x2 CTAs fits

__global__ __launch_bounds__(256, 2) void attn_mma(const float* __restrict__ qkv,
                                                   __half* __restrict__ outp) {
    extern __shared__ __align__(16) float sm[];
    const uint32_t sbase = smem_u32(sm);
    float* Ps = sm + PSOFF;

    const int tid  = threadIdx.x;
    const int wid  = tid >> 5;
    const int lane = tid & 31;
    const int g    = lane >> 2;
    const int tg   = lane & 3;
    const int q0   = blockIdx.x * AQ;
    const int h    = blockIdx.y;
    const int b    = blockIdx.z;
    const int qw   = q0 + wid * 16;

    const float* base  = qkv + (size_t)b * T_ * E3_ + h * DH_;
    const float* baseK = base + D_;
    const float* baseV = base + 2 * D_;

    float qa[8][4];
    {
        const float* Qr0 = base + (size_t)(qw + g) * E3_;
        const float* Qr1 = base + (size_t)(qw + 8 + g) * E3_;
#pragma unroll
        for (int ks = 0; ks < 8; ks++) {
            qa[ks][0] = Qr0[ks * 8 + tg] * SCALE_;
            qa[ks][1] = Qr1[ks * 8 + tg] * SCALE_;
            qa[ks][2] = Qr0[ks * 8 + tg + 4] * SCALE_;
            qa[ks][3] = Qr1[ks * 8 + tg + 4] * SCALE_;
        }
    }

    float O[8][4];
#pragma unroll
    for (int nt = 0; nt < 8; nt++)
#pragma unroll
        for (int i = 0; i < 4; i++) O[nt][i] = 0.f;
    float mrow[2] = {-1e30f, -1e30f};
    float lrow[2] = {0.f, 0.f};

    const int c_lo = (q0 > 255 ? q0 - 255 : 0) >> 6;
    const int c_hi = (q0 + AQ - 1) >> 6;

    const int ldr = tid >> 4;
    const int ldf = tid & 15;

    auto issue = [&](int c, int s) {
        const int k0 = c << 6;
        const uint32_t kb = sbase + (uint32_t)s * KCH * 4;
        const uint32_t vb = sbase + (2 * KCH + (uint32_t)s * VCH) * 4;
#pragma unroll
        for (int u = 0; u < 4; u++) {
            const int r = ldr + u * 16;
            cp_async16(kb + (r * KP + ldf * 4) * 4, baseK + (size_t)(k0 + r) * E3_ + ldf * 4);
            cp_async16(vb + (r * VP + ldf * 4) * 4, baseV + (size_t)(k0 + r) * E3_ + ldf * 4);
        }
        CP_COMMIT();
    };

    issue(c_lo, 0);

    for (int c = c_lo; c <= c_hi; c++) {
        const int k0 = c << 6;
        const int st = (c - c_lo) & 1;
        CP_WAIT0();
        __syncthreads();
        if (c < c_hi) issue(c + 1, st ^ 1);

        const float* Kb = sm + st * KCH;
        const float* Vb = sm + 2 * KCH + st * VCH;

        const bool active = !(k0 > qw + 15 || k0 < qw - 318);
        if (active) {
            float s[8][4];
#pragma unroll
            for (int nt = 0; nt < 8; nt++)
#pragma unroll
                for (int i = 0; i < 4; i++) s[nt][i] = 0.f;

#pragma unroll
            for (int ks = 0; ks < 8; ks++) {
                uint32_t a[4] = {__float_as_uint(qa[ks][0]), __float_as_uint(qa[ks][1]),
                                 __float_as_uint(qa[ks][2]), __float_as_uint(qa[ks][3])};
#pragma unroll
                for (int nt = 0; nt < 8; nt++) {
                    const float* kp = &Kb[(nt * 8 + g) * KP + ks * 8 + tg];
                    uint32_t bfr[2] = {__float_as_uint(kp[0]), __float_as_uint(kp[4])};
                    mma_tf32(s[nt], a, bfr);
                }
            }

#pragma unroll
            for (int nt = 0; nt < 8; nt++) {
#pragma unroll
                for (int p = 0; p < 2; p++) {
#pragma unroll
                    for (int j = 0; j < 2; j++) {
                        const int qr = qw + g + 8 * p;
                        const int kc = k0 + nt * 8 + 2 * tg + j;
                        const int d  = qr - kc;
                        if (!(d >= 0 && d < WIN_)) s[nt][p * 2 + j] = -1e30f;
                    }
                }
            }

#pragma unroll
            for (int p = 0; p < 2; p++) {
                float mx = -1e30f;
#pragma unroll
                for (int nt = 0; nt < 8; nt++) {
                    mx = fmaxf(mx, s[nt][p * 2 + 0]);
                    mx = fmaxf(mx, s[nt][p * 2 + 1]);
                }
                mx = fmaxf(mx, __shfl_xor_sync(0xffffffffu, mx, 1));
                mx = fmaxf(mx, __shfl_xor_sync(0xffffffffu, mx, 2));
                const float mnew = fmaxf(mrow[p], mx);
                float sum = 0.f;
#pragma unroll
                for (int nt = 0; nt < 8; nt++) {
#pragma unroll
                    for (int j = 0; j < 2; j++) {
                        const float v = s[nt][p * 2 + j];
                        const float pv = (v < -5e29f) ? 0.f : __expf(v - mnew);
                        s[nt][p * 2 + j] = pv;
                        sum += pv;
                    }
                }
                sum += __shfl_xor_sync(0xffffffffu, sum, 1);
                sum += __shfl_xor_sync(0xffffffffu, sum, 2);
                const float alpha = (mrow[p] < -5e29f) ? 0.f : __expf(mrow[p] - mnew);
                lrow[p] = lrow[p] * alpha + sum;
                mrow[p] = mnew;
#pragma unroll
                for (int nt = 0; nt < 8; nt++) {
                    O[nt][p * 2 + 0] *= alpha;
                    O[nt][p * 2 + 1] *= alpha;
                }
            }

            const int pr0 = wid * 16 + g;
            const int pr1 = pr0 + 8;
#pragma unroll
            for (int nt = 0; nt < 8; nt++) {
                *(float2*)&Ps[pr0 * 68 + nt * 8 + 2 * tg] =
                    make_float2(tf32r(s[nt][0]), tf32r(s[nt][1]));
                *(float2*)&Ps[pr1 * 68 + nt * 8 + 2 * tg] =
                    make_float2(tf32r(s[nt][2]), tf32r(s[nt][3]));
            }
            __syncwarp();

#pragma unroll
            for (int ks = 0; ks < 8; ks++) {
                const float* pp0 = &Ps[pr0 * 68 + ks * 8 + tg];
                const float* pp1 = &Ps[pr1 * 68 + ks * 8 + tg];
                uint32_t a[4] = {__float_as_uint(pp0[0]), __float_as_uint(pp1[0]),
                                 __float_as_uint(pp0[4]), __float_as_uint(pp1[4])};
#pragma unroll
                for (int nt = 0; nt < 8; nt++) {
                    const float* vp = &Vb[(ks * 8 + tg) * VP + nt * 8 + g];
                    uint32_t bfr[2] = {__float_as_uint(vp[0]), __float_as_uint(vp[4 * VP])};
                    mma_tf32(O[nt], a, bfr);
                }
            }
        }
        __syncthreads();
    }

    // Epilogue: normalize, convert to fp16, store 16-group permuted.
    // kk even pair (nt even): dst = 4tg, 4tg+1 ; kk=8.. (nt odd): dst = 4tg+2, +3.
    const float inv0 = 1.0f / lrow[0];
    const float inv1 = 1.0f / lrow[1];
    const int row0 = b * T_ + qw + g;
    const int row1 = row0 + 8;
#pragma unroll
    for (int nt = 0; nt < 8; nt++) {
        const int colb = h * DH_ + (nt >> 1) * 16;
        const int d0 = 4 * tg + 2 * (nt & 1);
        *(__half2*)(outp + (size_t)row0 * D_ + colb + d0) =
            __floats2half2_rn(O[nt][0] * inv0, O[nt][1] * inv0);
        *(__half2*)(outp + (size_t)row1 * D_ + colb + d0) =
            __floats2half2_rn(O[nt][2] * inv1, O[nt][3] * inv1);
    }
}

// ---------------------------------------------------------------------------
// Host launcher
// ---------------------------------------------------------------------------
extern "C" void kernel_launch(void* const* d_in, const int* in_sizes, int n_in,
                              void* d_out, int out_size) {
    (void)in_sizes; (void)n_in; (void)out_size;
    const float* x     = (const float*)d_in[0];   // [B,T,D]
    const float* w_qkv = (const float*)d_in[1];   // [3072,1024]
    const float* w_out = (const float*)d_in[2];   // [1024,1024]
    float* out = (float*)d_out;                   // [B,T,D]

    float *qkvbuf; __half *attbuf, *xh, *wqh, *woh;
    cudaGetSymbolAddress((void**)&qkvbuf, g_qkv);
    cudaGetSymbolAddress((void**)&attbuf, g_atth);
    cudaGetSymbolAddress((void**)&xh,     g_xh);
    cudaGetSymbolAddress((void**)&wqh,    g_wqh);
    cudaGetSymbolAddress((void**)&woh,    g_woh);

    cudaFuncSetAttribute(gemm_tc<true>,  cudaFuncAttributeMaxDynamicSharedMemorySize, GEMM_SMEM);
    cudaFuncSetAttribute(gemm_tc<false>, cudaFuncAttributeMaxDynamicSharedMemorySize, GEMM_SMEM);
    cudaFuncSetAttribute(attn_mma, cudaFuncAttributeMaxDynamicSharedMemorySize, ATT_SMEM);

    // 0) Fused fp32->fp16 convert + 16-group k-permute of all GEMM inputs
    {
        const int total = NX16 + NW16 + NO16;    // 524288
        preround_all<<<(total + 255) / 256, 256>>>(x, w_qkv, w_out, xh, wqh, woh);
    }

    // 1) QKV projection (fp16 mma; fp32 tf32-rounded output for attention)
    gemm_tc<true><<<dim3(E3_ / BN, M_ / BM), 256, GEMM_SMEM>>>(xh, wqh, qkvbuf, E3_, D_);

    // 2) Sliding-window attention (tf32 mma; writes fp16 16-permuted g_att)
    attn_mma<<<dim3(T_ / AQ, H_, B_), 256, ATT_SMEM>>>(qkvbuf, attbuf);

    // 3) Output projection (fp16 mma; final fp32 output)
    gemm_tc<false><<<dim3(D_ / BN, M_ / BM), 256, GEMM_SMEM>>>(attbuf, woh, out, D_, D_);
}

// round 12
// speedup vs baseline: 2.4477x; 1.0861x over previous
#include <cuda_runtime.h>
#include <cuda_fp16.h>
#include <cstdint>
#include <math.h>

// Problem constants
#define B_    2
#define T_    2048
#define D_    1024
#define H_    16
#define DH_   64
#define WIN_  256
#define E3_   3072          // 3*H*Dh
#define M_    (B_ * T_)     // 4096

// Scratch (static device globals — allocation-free per harness rules)
__device__ __half g_qkvh[(size_t)M_ * E3_];    // [4096,3072] fp16, natural
__device__ __half g_atth[(size_t)M_ * D_];     // [4096,1024] fp16, 16-permuted
__device__ __half g_xh[(size_t)M_ * D_];       // fp16 + 16-permuted x
__device__ __half g_wqh[(size_t)E3_ * D_];     // fp16 + 16-permuted w_qkv
__device__ __half g_woh[(size_t)D_ * D_];      // fp16 + 16-permuted w_out

// ===========================================================================
// Helpers
// ===========================================================================
__device__ __forceinline__ uint32_t smem_u32(const void* p) {
    uint32_t a;
    asm("{ .reg .u64 t; cvta.to.shared.u64 t, %1; cvt.u32.u64 %0, t; }" : "=r"(a) : "l"(p));
    return a;
}
__device__ __forceinline__ void cp_async16(uint32_t saddr, const void* gptr) {
    asm volatile("cp.async.cg.shared.global [%0], [%1], 16;" :: "r"(saddr), "l"(gptr));
}
#define CP_COMMIT() asm volatile("cp.async.commit_group;" ::: "memory")
#define CP_WAIT0()  asm volatile("cp.async.wait_group 0;" ::: "memory")

// fp16 mma: m16n8k16, fp32 accumulate
__device__ __forceinline__ void mma_f16(float* c, const uint32_t* a, const uint32_t* b) {
    asm volatile(
        "mma.sync.aligned.m16n8k16.row.col.f32.f16.f16.f32 "
        "{%0,%1,%2,%3}, {%4,%5,%6,%7}, {%8,%9}, {%0,%1,%2,%3};"
        : "+f"(c[0]), "+f"(c[1]), "+f"(c[2]), "+f"(c[3])
        : "r"(a[0]), "r"(a[1]), "r"(a[2]), "r"(a[3]), "r"(b[0]), "r"(b[1]));
}
__device__ __forceinline__ uint32_t h2u(__half2 h) { return *(uint32_t*)&h; }

// Fused fp32 -> fp16 convert + 16-group k-permute, all three operands.
// Within each 16 k-group: dst[4t+0..3] = src[2t, 2t+1, 2t+8, 2t+9].
#define NX16 (M_ * D_ / 16)
#define NW16 (E3_ * D_ / 16)
#define NO16 (D_ * D_ / 16)
__global__ void preround_all(const float* __restrict__ x,  const float* __restrict__ wq,
                             const float* __restrict__ wo, __half* __restrict__ xh,
                             __half* __restrict__ wqh,     __half* __restrict__ woh) {
    int i = blockIdx.x * blockDim.x + threadIdx.x;
    const float* s; __half* d; int j;
    if (i < NX16)             { s = x;  d = xh;  j = i; }
    else if (i < NX16 + NW16) { s = wq; d = wqh; j = i - NX16; }
    else if (i < NX16 + NW16 + NO16) { s = wo; d = woh; j = i - NX16 - NW16; }
    else return;
    const float4 v0 = ((const float4*)s)[4 * j + 0];
    const float4 v1 = ((const float4*)s)[4 * j + 1];
    const float4 v2 = ((const float4*)s)[4 * j + 2];
    const float4 v3 = ((const float4*)s)[4 * j + 3];
    __half2* o = (__half2*)(d + 16 * (size_t)j);
    o[0] = __floats2half2_rn(v0.x, v0.y);
    o[1] = __floats2half2_rn(v2.x, v2.y);
    o[2] = __floats2half2_rn(v0.z, v0.w);
    o[3] = __floats2half2_rn(v2.z, v2.w);
    o[4] = __floats2half2_rn(v1.x, v1.y);
    o[5] = __floats2half2_rn(v3.x, v3.y);
    o[6] = __floats2half2_rn(v1.z, v1.w);
    o[7] = __floats2half2_rn(v3.z, v3.w);
}

// ===========================================================================
// fp16 warp-MMA NT GEMM on 16-permuted inputs (round-11 proven).
// OUTH=true: fp16 natural output; OUTH=false: fp32 output.
// ===========================================================================
#define BM 128
#define BN 128
#define BK 32
#define PITCH 80
#define STAGE_HALVES (2 * 128 * PITCH)
#define GEMM_SMEM (2 * STAGE_HALVES * 2)           // 81920 B

template <bool OUTH>
__global__ __launch_bounds__(256, 2) void gemm_tc(const __half* __restrict__ A,
                                                  const __half* __restrict__ B,
                                                  void* __restrict__ Cv,
                                                  int Ndim, int Kdim) {
    extern __shared__ __align__(16) __half smh[];
    const uint32_t sbase = smem_u32(smh);

    const int tid  = threadIdx.x;
    const int wid  = tid >> 5;
    const int lane = tid & 31;
    const int g    = lane >> 2;
    const int tg   = lane & 3;
    const int m0   = blockIdx.y * BM;
    const int n0   = blockIdx.x * BN;
    const int wm   = wid & 1;
    const int wn   = wid >> 1;

    const int lr = tid >> 2;     // staging row 0..63 (x2 via +64 offset)
    const int lf = tid & 3;      // 16B chunk within 32-half k-row

    const uint32_t sa0 = sbase + (lr * PITCH + lf * 8) * 2;
    const uint32_t sb0 = sa0 + 128 * PITCH * 2;
    const __half* Ap0 = A + (size_t)(m0 + lr) * Kdim + lf * 8;
    const __half* Bp0 = B + (size_t)(n0 + lr) * Kdim + lf * 8;

    float c[4][4][4];
#pragma unroll
    for (int mt = 0; mt < 4; mt++)
#pragma unroll
        for (int nt = 0; nt < 4; nt++)
#pragma unroll
            for (int i = 0; i < 4; i++) c[mt][nt][i] = 0.f;

    const int NK = Kdim / BK;

    {
#pragma unroll
        for (int u = 0; u < 2; u++) {
            cp_async16(sa0 + u * 64 * PITCH * 2, Ap0 + (size_t)u * 64 * Kdim);
            cp_async16(sb0 + u * 64 * PITCH * 2, Bp0 + (size_t)u * 64 * Kdim);
        }
        CP_COMMIT();
    }

    for (int kt = 0; kt < NK; kt++) {
        CP_WAIT0();
        __syncthreads();

        if (kt + 1 < NK) {
            const uint32_t off = (uint32_t)((kt + 1) & 1) * STAGE_HALVES * 2;
            const int kc = (kt + 1) * BK;
#pragma unroll
            for (int u = 0; u < 2; u++) {
                cp_async16(sa0 + off + u * 64 * PITCH * 2, Ap0 + kc + (size_t)u * 64 * Kdim);
                cp_async16(sb0 + off + u * 64 * PITCH * 2, Bp0 + kc + (size_t)u * 64 * Kdim);
            }
            CP_COMMIT();
        }

        const __half* Ab = smh + (kt & 1) * STAGE_HALVES;
        const __half* Bb = Ab + 128 * PITCH;

#pragma unroll
        for (int kp = 0; kp < 2; kp++) {
            const int ko = kp * 16 + 4 * tg;
            uint32_t af[4][4], bf[4][2];
#pragma unroll
            for (int mt = 0; mt < 4; mt++) {
                const int r = wm * 64 + mt * 16 + g;
                const uint2 u0 = *(const uint2*)(Ab + r * PITCH + ko);
                const uint2 u1 = *(const uint2*)(Ab + (r + 8) * PITCH + ko);
                af[mt][0] = u0.x;
                af[mt][1] = u1.x;
                af[mt][2] = u0.y;
                af[mt][3] = u1.y;
            }
#pragma unroll
            for (int nt = 0; nt < 4; nt++) {
                const int n = wn * 32 + nt * 8 + g;
                const uint2 q = *(const uint2*)(Bb + n * PITCH + ko);
                bf[nt][0] = q.x;
                bf[nt][1] = q.y;
            }
#pragma unroll
            for (int mt = 0; mt < 4; mt++)
#pragma unroll
                for (int nt = 0; nt < 4; nt++)
                    mma_f16(c[mt][nt], af[mt], bf[nt]);
        }
    }

    // Epilogue (natural column order)
#pragma unroll
    for (int mt = 0; mt < 4; mt++) {
        const int row = m0 + wm * 64 + mt * 16 + g;
#pragma unroll
        for (int nt = 0; nt < 4; nt++) {
            const int col = n0 + wn * 32 + nt * 8 + 2 * tg;
            if (OUTH) {
                __half* C = (__half*)Cv;
                *(__half2*)(C + (size_t)row * Ndim + col) =
                    __floats2half2_rn(c[mt][nt][0], c[mt][nt][1]);
                *(__half2*)(C + (size_t)(row + 8) * Ndim + col) =
                    __floats2half2_rn(c[mt][nt][2], c[mt][nt][3]);
            } else {
                float* C = (float*)Cv;
                *(float2*)(C + (size_t)row * Ndim + col) =
                    make_float2(c[mt][nt][0], c[mt][nt][1]);
                *(float2*)(C + (size_t)(row + 8) * Ndim + col) =
                    make_float2(c[mt][nt][2], c[mt][nt][3]);
            }
        }
    }
}

// ===========================================================================
// Sliding-window attention, ALL-fp16 mma (m16n8k16), fp32 softmax.
// Block = 128 queries x head x batch, 8 warps x 16 query rows, 2 CTA/SM.
// K staged natural via cp.async; V staged TRANSPOSED (LDG prefetch + STS).
// P staged fp16. Epilogue: fp16 g_att, 16-group permuted (for gemm2).
// ===========================================================================
#define AQ 128
#define KP2 72                       // halves per K row   (bank-verified)
#define VP2 72                       // halves per VT row
#define PP2 72                       // halves per P row
#define KCH2 (64 * KP2)              // 4608 halves
#define VCH2 (64 * VP2)              // 4608
#define PS2OFF (2 * KCH2 + 2 * VCH2) // 18432 halves
#define ATT_SMEM ((PS2OFF + 128 * PP2) * 2)   // 55296 B

__global__ __launch_bounds__(256, 2) void attn_mma(const __half* __restrict__ qkv,
                                                   __half* __restrict__ outp) {
    extern __shared__ __align__(16) __half smh[];
    const uint32_t sbase = smem_u32(smh);
    __half* Pp = smh + PS2OFF;

    const int tid  = threadIdx.x;
    const int wid  = tid >> 5;
    const int lane = tid & 31;
    const int g    = lane >> 2;
    const int tg   = lane & 3;
    const int q0   = blockIdx.x * AQ;
    const int h    = blockIdx.y;
    const int b    = blockIdx.z;
    const int qw   = q0 + wid * 16;

    const __half* base  = qkv + (size_t)b * T_ * E3_ + h * DH_;
    const __half* baseK = base + D_;
    const __half* baseV = base + 2 * D_;

    // Q fragments (fp16, scaled by 0.125 — exact power of two)
    uint32_t qa[4][4];
    {
        const __half2 sc2 = __half2half2(__float2half_rn(0.125f));
        const __half* Qr0 = base + (size_t)(qw + g) * E3_;
        const __half* Qr1 = base + (size_t)(qw + 8 + g) * E3_;
#pragma unroll
        for (int ks = 0; ks < 4; ks++) {
            const int ko = ks * 16 + 2 * tg;
            qa[ks][0] = h2u(__hmul2(*(const __half2*)(Qr0 + ko), sc2));
            qa[ks][1] = h2u(__hmul2(*(const __half2*)(Qr1 + ko), sc2));
            qa[ks][2] = h2u(__hmul2(*(const __half2*)(Qr0 + ko + 8), sc2));
            qa[ks][3] = h2u(__hmul2(*(const __half2*)(Qr1 + ko + 8), sc2));
        }
    }

    float O[8][4];
#pragma unroll
    for (int nt = 0; nt < 8; nt++)
#pragma unroll
        for (int i = 0; i < 4; i++) O[nt][i] = 0.f;
    float mrow[2] = {-1e30f, -1e30f};
    float lrow[2] = {0.f, 0.f};

    const int c_lo = (q0 > 255 ? q0 - 255 : 0) >> 6;
    const int c_hi = (q0 + AQ - 1) >> 6;

    // K staging: thread covers row kr, 16B chunks kf and kf+4
    const int kr = tid >> 2;
    const int kf = tid & 3;
    auto issueK = [&](int c, int s) {
        const int k0 = c << 6;
        const uint32_t kb = sbase + (uint32_t)s * KCH2 * 2;
        const __half* src = baseK + (size_t)(k0 + kr) * E3_;
        cp_async16(kb + (kr * KP2 + kf * 8) * 2, src + kf * 8);
        cp_async16(kb + (kr * KP2 + (kf + 4) * 8) * 2, src + (kf + 4) * 8);
        CP_COMMIT();
    };

    // V prefetch into registers (2 x 8 halves per thread), then STS transposed
    uint4 vreg[2];
    auto loadV = [&](int c) {
        const int k0 = c << 6;
#pragma unroll
        for (int p = 0; p < 2; p++) {
            const int idx = tid + p * 256;
            const int r = idx & 63;
            const int f = idx >> 6;      // 0..7
            vreg[p] = *(const uint4*)(baseV + (size_t)(k0 + r) * E3_ + f * 8);
        }
    };
    auto storeVT = [&](int s) {
        __half* vt = smh + 2 * KCH2 + s * VCH2;
#pragma unroll
        for (int p = 0; p < 2; p++) {
            const int idx = tid + p * 256;
            const int r = idx & 63;
            const int f = idx >> 6;
            const __half* hv = (const __half*)&vreg[p];
#pragma unroll
            for (int j = 0; j < 8; j++)
                vt[(f * 8 + j) * VP2 + r] = hv[j];
        }
    };

    issueK(c_lo, 0);
    loadV(c_lo);

    for (int c = c_lo; c <= c_hi; c++) {
        const int k0 = c << 6;
        const int st = (c - c_lo) & 1;
        CP_WAIT0();
        __syncthreads();                   // K(c) landed; compute(c-1) done
        storeVT(st);
        if (c < c_hi) { issueK(c + 1, st ^ 1); loadV(c + 1); }
        __syncthreads();                   // VT(c) visible

        const __half* Kb = smh + st * KCH2;
        const __half* Vt = smh + 2 * KCH2 + st * VCH2;

        const bool active = !(k0 > qw + 15 || k0 < qw - 318);
        if (active) {
            // S = Q @ K^T  (16 rows x 64 keys, fp16 mma)
            float s[8][4];
#pragma unroll
            for (int nt = 0; nt < 8; nt++)
#pragma unroll
                for (int i = 0; i < 4; i++) s[nt][i] = 0.f;

#pragma unroll
            for (int ks = 0; ks < 4; ks++) {
#pragma unroll
                for (int nt = 0; nt < 8; nt++) {
                    const __half* kp = Kb + (nt * 8 + g) * KP2 + ks * 16 + 2 * tg;
                    uint32_t bf[2] = {*(const uint32_t*)kp, *(const uint32_t*)(kp + 8)};
                    mma_f16(s[nt], qa[ks], bf);
                }
            }

            // Sliding causal window mask
#pragma unroll
            for (int nt = 0; nt < 8; nt++) {
#pragma unroll
                for (int p = 0; p < 2; p++) {
#pragma unroll
                    for (int j = 0; j < 2; j++) {
                        const int qr = qw + g + 8 * p;
                        const int kc = k0 + nt * 8 + 2 * tg + j;
                        const int d  = qr - kc;
                        if (!(d >= 0 && d < WIN_)) s[nt][p * 2 + j] = -1e30f;
                    }
                }
            }

            // Online softmax (fp32, quad-reduced)
#pragma unroll
            for (int p = 0; p < 2; p++) {
                float mx = -1e30f;
#pragma unroll
                for (int nt = 0; nt < 8; nt++) {
                    mx = fmaxf(mx, s[nt][p * 2 + 0]);
                    mx = fmaxf(mx, s[nt][p * 2 + 1]);
                }
                mx = fmaxf(mx, __shfl_xor_sync(0xffffffffu, mx, 1));
                mx = fmaxf(mx, __shfl_xor_sync(0xffffffffu, mx, 2));
                const float mnew = fmaxf(mrow[p], mx);
                float sum = 0.f;
#pragma unroll
                for (int nt = 0; nt < 8; nt++) {
#pragma unroll
                    for (int j = 0; j < 2; j++) {
                        const float v = s[nt][p * 2 + j];
                        const float pv = (v < -5e29f) ? 0.f : __expf(v - mnew);
                        s[nt][p * 2 + j] = pv;
                        sum += pv;
                    }
                }
                sum += __shfl_xor_sync(0xffffffffu, sum, 1);
                sum += __shfl_xor_sync(0xffffffffu, sum, 2);
                const float alpha = (mrow[p] < -5e29f) ? 0.f : __expf(mrow[p] - mnew);
                lrow[p] = lrow[p] * alpha + sum;
                mrow[p] = mnew;
#pragma unroll
                for (int nt = 0; nt < 8; nt++) {
                    O[nt][p * 2 + 0] *= alpha;
                    O[nt][p * 2 + 1] *= alpha;
                }
            }

            // Stage P as fp16 (warp-private rows)
            const int pr0 = wid * 16 + g;
            const int pr1 = pr0 + 8;
#pragma unroll
            for (int nt = 0; nt < 8; nt++) {
                *(__half2*)(Pp + pr0 * PP2 + nt * 8 + 2 * tg) =
                    __floats2half2_rn(s[nt][0], s[nt][1]);
                *(__half2*)(Pp + pr1 * PP2 + nt * 8 + 2 * tg) =
                    __floats2half2_rn(s[nt][2], s[nt][3]);
            }
            __syncwarp();

            // O += P @ V  (VT[d][kseq]; k dim = kseq, fp16 mma)
#pragma unroll
            for (int ks = 0; ks < 4; ks++) {
                const __half* pp0 = Pp + pr0 * PP2 + ks * 16 + 2 * tg;
                const __half* pp1 = Pp + pr1 * PP2 + ks * 16 + 2 * tg;
                uint32_t a[4] = {*(const uint32_t*)pp0, *(const uint32_t*)pp1,
                                 *(const uint32_t*)(pp0 + 8), *(const uint32_t*)(pp1 + 8)};
#pragma unroll
                for (int nt = 0; nt < 8; nt++) {
                    const __half* vp = Vt + (nt * 8 + g) * VP2 + ks * 16 + 2 * tg;
                    uint32_t bf[2] = {*(const uint32_t*)vp, *(const uint32_t*)(vp + 8)};
                    mma_f16(O[nt], a, bf);
                }
            }
        }
        __syncthreads();   // all done with stage st before refill next iter
    }

    // Epilogue: normalize, fp16, 16-group permuted store for gemm2.
    const float inv0 = 1.0f / lrow[0];
    const float inv1 = 1.0f / lrow[1];
    const int row0 = b * T_ + qw + g;
    const int row1 = row0 + 8;
#pragma unroll
    for (int nt = 0; nt < 8; nt++) {
        const int colb = h * DH_ + (nt >> 1) * 16;
        const int d0 = 4 * tg + 2 * (nt & 1);
        *(__half2*)(outp + (size_t)row0 * D_ + colb + d0) =
            __floats2half2_rn(O[nt][0] * inv0, O[nt][1] * inv0);
        *(__half2*)(outp + (size_t)row1 * D_ + colb + d0) =
            __floats2half2_rn(O[nt][2] * inv1, O[nt][3] * inv1);
    }
}

// ---------------------------------------------------------------------------
// Host launcher
// ---------------------------------------------------------------------------
extern "C" void kernel_launch(void* const* d_in, const int* in_sizes, int n_in,
                              void* d_out, int out_size) {
    (void)in_sizes; (void)n_in; (void)out_size;
    const float* x     = (const float*)d_in[0];   // [B,T,D]
    const float* w_qkv = (const float*)d_in[1];   // [3072,1024]
    const float* w_out = (const float*)d_in[2];   // [1024,1024]
    float* out = (float*)d_out;                   // [B,T,D]

    __half *qkvh, *attbuf, *xh, *wqh, *woh;
    cudaGetSymbolAddress((void**)&qkvh,   g_qkvh);
    cudaGetSymbolAddress((void**)&attbuf, g_atth);
    cudaGetSymbolAddress((void**)&xh,     g_xh);
    cudaGetSymbolAddress((void**)&wqh,    g_wqh);
    cudaGetSymbolAddress((void**)&woh,    g_woh);

    cudaFuncSetAttribute(gemm_tc<true>,  cudaFuncAttributeMaxDynamicSharedMemorySize, GEMM_SMEM);
    cudaFuncSetAttribute(gemm_tc<false>, cudaFuncAttributeMaxDynamicSharedMemorySize, GEMM_SMEM);
    cudaFuncSetAttribute(attn_mma, cudaFuncAttributeMaxDynamicSharedMemorySize, ATT_SMEM);

    // 0) Fused fp32->fp16 convert + 16-group k-permute of all GEMM inputs
    {
        const int total = NX16 + NW16 + NO16;    // 524288
        preround_all<<<(total + 255) / 256, 256>>>(x, w_qkv, w_out, xh, wqh, woh);
    }

    // 1) QKV projection (fp16 mma; fp16 NATURAL output for attention)
    gemm_tc<true><<<dim3(E3_ / BN, M_ / BM), 256, GEMM_SMEM>>>(xh, wqh, qkvh, E3_, D_);

    // 2) Sliding-window attention (fp16 mma; writes fp16 16-permuted g_att)
    attn_mma<<<dim3(T_ / AQ, H_, B_), 256, ATT_SMEM>>>(qkvh, attbuf);

    // 3) Output projection (fp16 mma; final fp32 output)
    gemm_tc<false><<<dim3(D_ / BN, M_ / BM), 256, GEMM_SMEM>>>(attbuf, woh, out, D_, D_);
}